// round 3
// baseline (speedup 1.0000x reference)
#include <cuda_runtime.h>
#include <math.h>

#define Bb 8
#define Cc 16
#define WD 192
#define HT 192
#define NPIX (WD*HT)
#define Hh 4
#define HID 16
#define OCH 32
#define W2 214
#define SDIM 144

// ---------------- device scratch (no allocations allowed) ----------------
__device__ float g_Wq[Hh][HID][SDIM];
__device__ float g_Wk[Hh][128][SDIM];
__device__ float g_Wv[Hh][128][SDIM];
__device__ float g_S[Bb*Hh][SDIM*SDIM];
__device__ float g_W2[Bb][Hh][OCH][SDIM];
__device__ float g_bnsum[OCH];
__device__ float g_bnsq[OCH];

__constant__ int c_shift[4] = {1, 2, 4, 8};
__constant__ int c_off[8]   = {0, 1, 2, 5, 8, 7, 6, 3}; // position of the -1 tap per contrast kernel

// ---------------- kernel 1: fold blend kernels into effective conv weights ----------------
__global__ void k_prep(const float* __restrict__ wq, const float* __restrict__ wk,
                       const float* __restrict__ wv, const float* __restrict__ sum_w) {
    int h = blockIdx.x;
    int t = threadIdx.x;
    __shared__ float wcen[Cc][9];
    __shared__ float wsur[Cc][8][9];

    if (t < Cc * 9) {
        int c = t / 9, d = t % 9;
        float sw = sum_w[h * Cc + c];
        float su_f = (d == 4) ? 0.125f : (7.0f / 64.0f);
        float ce   = (d == 4) ? 1.0f : 0.0f;
        wcen[c][d] = su_f * (1.0f - sw) + ce * sw;
    }
    for (int idx = t; idx < Cc * 8 * 9; idx += 256) {
        int c = idx / 72;
        int k = (idx / 9) % 8;
        int d = idx % 9;
        float sw = sum_w[h * Cc + c];
        float delta = ((d == 4) ? 1.0f : 0.0f) + ((d == c_off[k]) ? -1.0f : 0.0f);
        float ce    = (d == 4) ? 1.0f : 0.0f;
        float k2w   = (delta - ce) * 1.125f + 0.125f;
        wsur[c][k][d] = delta * (1.0f - sw) + k2w * sw;
    }
    __syncthreads();

    for (int idx = t; idx < HID * SDIM; idx += 256) {
        int q = idx / SDIM, c = (idx % SDIM) / 9, d = idx % 9;
        g_Wq[h][q][c * 9 + d] = wq[(h * HID + q) * Cc + c] * wcen[c][d];
    }
    for (int idx = t; idx < 128 * SDIM; idx += 256) {
        int o = idx / SDIM, c = (idx % SDIM) / 9, d = idx % 9;
        float ak = 0.0f, av = 0.0f;
        #pragma unroll
        for (int k = 0; k < 8; k++) {
            float ws = wsur[c][k][d];
            ak = fmaf(wk[(h * 128 + o) * 128 + k * Cc + c], ws, ak);
            av = fmaf(wv[(h * 128 + o) * 128 + k * Cc + c], ws, av);
        }
        g_Wk[h][o][c * 9 + d] = ak;
        g_Wv[h][o][c * 9 + d] = av;
    }
}

// ---------------- kernel 2: zero scratch accumulators ----------------
__global__ void k_zero() {
    long total = (long)Bb * Hh * SDIM * SDIM;
    float* p = &g_S[0][0];
    for (long i = (long)blockIdx.x * 256 + threadIdx.x; i < total; i += (long)gridDim.x * 256)
        p[i] = 0.0f;
    if (blockIdx.x == 0 && threadIdx.x < OCH) {
        g_bnsum[threadIdx.x] = 0.0f;
        g_bnsq[threadIdx.x]  = 0.0f;
    }
}

// ---------------- kernel 3: S = X X^T, upper triangle only (symmetry) ----------------
// grid (24 x-groups of 8 rows, Hh, Bb), 288 threads:
//   slots 0..31   : 16 diagonal tiles x 2 y-halves
//   slots 32..271 : 120 off-diagonal (ti<tj) tiles x 2 y-halves
//   slots 272..287: idle (smem fill only)
__global__ void __launch_bounds__(288, 2) k_S(const float* __restrict__ cen) {
    __shared__ float sm[Cc * 3 * W2];
    int xg = blockIdx.x, h = blockIdx.y, b = blockIdx.z;
    int s = c_shift[h];
    int t = threadIdx.x;

    int ti = 0, tj = 0, half = 0;
    bool active = (t < 272);
    if (t < 32) {
        ti = tj = t & 15;
        half = t >> 4;
    } else if (active) {
        int s2 = t - 32;
        int p = s2 >> 1;
        half = s2 & 1;
        int rem = p;
        while (rem >= 15 - ti) { rem -= 15 - ti; ti++; }
        tj = ti + 1 + rem;
    }
    int ybeg = active ? half * 96 : 0;
    int yend = active ? ybeg + 96 : 0;

    float acc[81];
    #pragma unroll
    for (int i = 0; i < 81; i++) acc[i] = 0.0f;

    const float* cb = cen + (size_t)b * Cc * NPIX;
    int plen = HT + 2 * s;

    for (int xr = 0; xr < 8; xr++) {
        int x = xg * 8 + xr;
        __syncthreads();
        for (int idx = t; idx < Cc * 3 * plen; idx += 288) {
            int c = idx / (3 * plen);
            int rem = idx - c * 3 * plen;
            int r = rem / plen;
            int p = rem - r * plen;
            int xx = x + (r - 1) * s;
            int y = p - s;
            float v = 0.0f;
            if (xx >= 0 && xx < WD && y >= 0 && y < HT)
                v = cb[((size_t)c * WD + xx) * HT + y];
            sm[c * (3 * W2) + r * W2 + p] = v;
        }
        __syncthreads();

        const float* pa = sm + ti * (3 * W2);
        const float* pb = sm + tj * (3 * W2);
        #pragma unroll 4
        for (int y = ybeg; y < yend; y++) {
            float a[9], bbv[9];
            #pragma unroll
            for (int i = 0; i < 9; i++) a[i] = pa[(i / 3) * W2 + (i % 3) * s + y];
            #pragma unroll
            for (int j = 0; j < 9; j++) bbv[j] = pb[(j / 3) * W2 + (j % 3) * s + y];
            #pragma unroll
            for (int i = 0; i < 9; i++)
                #pragma unroll
                for (int j = 0; j < 9; j++)
                    acc[i * 9 + j] = fmaf(a[i], bbv[j], acc[i * 9 + j]);
        }
    }

    if (active) {
        float* Sg = g_S[b * Hh + h];
        #pragma unroll
        for (int i = 0; i < 9; i++)
            #pragma unroll
            for (int j = 0; j < 9; j++)
                atomicAdd(&Sg[(ti * 9 + i) * SDIM + (tj * 9 + j)], acc[i * 9 + j]);
    }
}

// ---------------- kernel 3b: mirror upper triangle of S into lower ----------------
__global__ void k_mirror() {
    float* Sg = g_S[blockIdx.x];
    for (int idx = threadIdx.x; idx < SDIM * SDIM; idx += blockDim.x) {
        int r = idx / SDIM, c = idx - r * SDIM;
        if (r > c) Sg[idx] = Sg[c * SDIM + r];
    }
}

// ---------------- kernel 4: per (b,h) attention head from S (smem-resident) ----------------
// dyn smem layout (floats):
//   S_sm  [144 x 145]  @0        (20880)
//   Wk_sm [128 x 145]  @20880    (18560)   (overlaid by M[32x128] after softmax)
//   Wq_sm [16 x 144]   @39440    (2304)
//   T_sm  [16 x 144]   @41744    (2304)
//   G     [16 x 128]   @44048    (2048)    total 46096 floats = 184384 B
__global__ void __launch_bounds__(512) k_attn(const float* __restrict__ w_out) {
    extern __shared__ float pool[];
    float* S_sm  = pool;
    float* Wk_sm = pool + 20880;
    float* Wq_sm = pool + 39440;
    float* T_sm  = pool + 41744;
    float* G     = pool + 44048;
    float* M     = Wk_sm;          // overlay after Wk is consumed
    __shared__ float nq[16], nk[128], red[512];

    int bh = blockIdx.x;
    int b = bh >> 2, h = bh & 3;
    int t = threadIdx.x;
    const float* Sg = g_S[bh];

    for (int idx = t; idx < SDIM * SDIM; idx += 512) {
        int r = idx / SDIM, c = idx - r * SDIM;
        S_sm[r * 145 + c] = Sg[idx];
    }
    for (int idx = t; idx < 128 * SDIM; idx += 512) {
        int r = idx / SDIM, c = idx - r * SDIM;
        Wk_sm[r * 145 + c] = (&g_Wk[h][0][0])[idx];
    }
    for (int idx = t; idx < 16 * SDIM; idx += 512)
        Wq_sm[idx] = (&g_Wq[h][0][0])[idx];
    __syncthreads();

    // T = Wq * S
    for (int idx = t; idx < 16 * SDIM; idx += 512) {
        int q = idx / SDIM, i = idx - q * SDIM;
        float a = 0.0f;
        #pragma unroll 4
        for (int j = 0; j < SDIM; j++)
            a = fmaf(Wq_sm[q * SDIM + j], S_sm[j * 145 + i], a);
        T_sm[idx] = a;
    }
    __syncthreads();

    // ||Q_q||^2 = T_q . Wq_q
    if (t < 16) {
        float a = 0.0f;
        for (int i = 0; i < SDIM; i++)
            a = fmaf(T_sm[t * SDIM + i], Wq_sm[t * SDIM + i], a);
        nq[t] = fmaxf(sqrtf(fmaxf(a, 0.0f)), 1e-12f);
    }

    // G[q][k] = T_q . Wk_k
    for (int idx = t; idx < 2048; idx += 512) {
        int q = idx >> 7, k = idx & 127;
        float a = 0.0f;
        #pragma unroll 4
        for (int i = 0; i < SDIM; i++)
            a = fmaf(T_sm[q * SDIM + i], Wk_sm[k * 145 + i], a);
        G[idx] = a;
    }

    // ||K_k||^2 = Wk_k S Wk_k^T  (128 k x 4 row-groups of 36)
    {
        int k = t & 127, g = t >> 7;
        float a = 0.0f;
        for (int i = g * 36; i < g * 36 + 36; i++) {
            float rd = 0.0f;
            #pragma unroll 4
            for (int j = 0; j < SDIM; j++)
                rd = fmaf(S_sm[i * 145 + j], Wk_sm[k * 145 + j], rd);
            a = fmaf(Wk_sm[k * 145 + i], rd, a);
        }
        red[t] = a;
    }
    __syncthreads();
    if (t < 128) {
        float sum = red[t] + red[t + 128] + red[t + 256] + red[t + 384];
        nk[t] = fmaxf(sqrtf(fmaxf(sum, 0.0f)), 1e-12f);
    }
    __syncthreads();

    // score = G / (|Q||K| sqrt(N)); sqrt(36864) = 192
    for (int idx = t; idx < 2048; idx += 512) {
        int q = idx >> 7, k = idx & 127;
        G[idx] = G[idx] / (nq[q] * nk[k] * 192.0f);
    }
    __syncthreads();

    // instance norm over 16x128
    float lsum = 0.0f;
    for (int idx = t; idx < 2048; idx += 512) lsum += G[idx];
    red[t] = lsum; __syncthreads();
    for (int st = 256; st > 0; st >>= 1) { if (t < st) red[t] += red[t + st]; __syncthreads(); }
    float mean = red[0] * (1.0f / 2048.0f);
    __syncthreads();
    float lss = 0.0f;
    for (int idx = t; idx < 2048; idx += 512) { float d = G[idx] - mean; lss = fmaf(d, d, lss); }
    red[t] = lss; __syncthreads();
    for (int st = 256; st > 0; st >>= 1) { if (t < st) red[t] += red[t + st]; __syncthreads(); }
    float var = red[0] * (1.0f / 2048.0f);
    float iscale = rsqrtf(var + 1e-5f);
    __syncthreads();
    for (int idx = t; idx < 2048; idx += 512)
        G[idx] = (G[idx] - mean) * iscale;
    __syncthreads();

    // softmax over k per row (16 warps x 1 row)
    int wid = t >> 5, lane = t & 31;
    {
        int q = wid;
        float m = -1e30f;
        for (int k = lane; k < 128; k += 32) m = fmaxf(m, G[q * 128 + k]);
        #pragma unroll
        for (int o = 16; o > 0; o >>= 1) m = fmaxf(m, __shfl_xor_sync(0xffffffffu, m, o));
        float ssum = 0.0f;
        for (int k = lane; k < 128; k += 32) {
            float e = expf(G[q * 128 + k] - m);
            G[q * 128 + k] = e;
            ssum += e;
        }
        #pragma unroll
        for (int o = 16; o > 0; o >>= 1) ssum += __shfl_xor_sync(0xffffffffu, ssum, o);
        float inv = 1.0f / ssum;
        for (int k = lane; k < 128; k += 32) G[q * 128 + k] *= inv;
    }
    __syncthreads();

    // M[o][k] = sum_q w_out[o, h*16+q] attn[q][k]   (M overlays Wk_sm)
    float mv[8];
    {
        #pragma unroll
        for (int r = 0; r < 8; r++) {
            int idx = t + r * 512;
            int o = idx >> 7, k = idx & 127;
            float a = 0.0f;
            #pragma unroll
            for (int q = 0; q < 16; q++)
                a = fmaf(w_out[o * 64 + h * 16 + q], G[q * 128 + k], a);
            mv[r] = a;
        }
    }
    __syncthreads();   // all reads of Wk_sm done before overlay write
    #pragma unroll
    for (int r = 0; r < 8; r++) M[t + r * 512] = mv[r];
    __syncthreads();

    // Weff2[o][i] = sum_k M[o][k] Wv[k][i]
    for (int idx = t; idx < OCH * SDIM; idx += 512) {
        int o = idx / SDIM, i = idx - o * SDIM;
        float a = 0.0f;
        #pragma unroll 4
        for (int k = 0; k < 128; k++)
            a = fmaf(M[o * 128 + k], g_Wv[h][k][i], a);
        g_W2[b][h][o][i] = a;
    }
}

// ---------------- kernel 5: fused output conv (4 dilated 3x3 convs) + BN stats ----------------
// grid (48 x-groups of 4 rows, Bb), 256 threads = 8 warps (o-groups of 4) x 32 lanes (y-groups of 6)
__global__ void __launch_bounds__(256) k_out(const float* __restrict__ cen, float* __restrict__ out) {
    extern __shared__ float dsm[];
    float* insm = dsm;                 // Cc*3*W2 = 10272 floats
    float* W2sm = dsm + Cc * 3 * W2;   // OCH*SDIM = 4608 floats

    int xg = blockIdx.x, b = blockIdx.y;
    int t = threadIdx.x;
    int ty = t & 31, to = t >> 5;
    const float* cb = cen + (size_t)b * Cc * NPIX;

    for (int xr = 0; xr < 4; xr++) {
        int x = xg * 4 + xr;
        float acc[4][6];
        #pragma unroll
        for (int oo = 0; oo < 4; oo++)
            #pragma unroll
            for (int j = 0; j < 6; j++) acc[oo][j] = 0.0f;

        for (int h = 0; h < Hh; h++) {
            int s = c_shift[h];
            int plen = HT + 2 * s;
            __syncthreads();
            for (int idx = t; idx < Cc * 3 * plen; idx += 256) {
                int c = idx / (3 * plen);
                int rem = idx - c * 3 * plen;
                int r = rem / plen;
                int p = rem - r * plen;
                int xx = x + (r - 1) * s;
                int y = p - s;
                float v = 0.0f;
                if (xx >= 0 && xx < WD && y >= 0 && y < HT)
                    v = cb[((size_t)c * WD + xx) * HT + y];
                insm[c * (3 * W2) + r * W2 + p] = v;
            }
            for (int idx = t; idx < OCH * SDIM; idx += 256)
                W2sm[idx] = (&g_W2[b][h][0][0])[idx];
            __syncthreads();

            int ybase = ty * 6;
            #pragma unroll 1
            for (int c = 0; c < Cc; c++) {
                const float* pc = insm + c * (3 * W2);
                #pragma unroll
                for (int d = 0; d < 9; d++) {
                    const float* px = pc + (d / 3) * W2 + (d % 3) * s + ybase;
                    float w0 = W2sm[(to * 4 + 0) * SDIM + c * 9 + d];
                    float w1 = W2sm[(to * 4 + 1) * SDIM + c * 9 + d];
                    float w2 = W2sm[(to * 4 + 2) * SDIM + c * 9 + d];
                    float w3 = W2sm[(to * 4 + 3) * SDIM + c * 9 + d];
                    #pragma unroll
                    for (int j = 0; j < 6; j++) {
                        float xv = px[j];
                        acc[0][j] = fmaf(w0, xv, acc[0][j]);
                        acc[1][j] = fmaf(w1, xv, acc[1][j]);
                        acc[2][j] = fmaf(w2, xv, acc[2][j]);
                        acc[3][j] = fmaf(w3, xv, acc[3][j]);
                    }
                }
            }
        }

        // write raw y + accumulate BN stats
        #pragma unroll
        for (int oo = 0; oo < 4; oo++) {
            int o = to * 4 + oo;
            float s1 = 0.0f, s2 = 0.0f;
            float* op = out + (((size_t)b * OCH + o) * WD + x) * HT + ty * 6;
            #pragma unroll
            for (int j = 0; j < 6; j++) {
                float v = acc[oo][j];
                op[j] = v;
                s1 += v;
                s2 = fmaf(v, v, s2);
            }
            #pragma unroll
            for (int off2 = 16; off2 > 0; off2 >>= 1) {
                s1 += __shfl_xor_sync(0xffffffffu, s1, off2);
                s2 += __shfl_xor_sync(0xffffffffu, s2, off2);
            }
            if (ty == 0) {
                atomicAdd(&g_bnsum[o], s1);
                atomicAdd(&g_bnsq[o], s2);
            }
        }
    }
}

// ---------------- kernel 6: batchnorm (train stats) + ReLU, in place ----------------
__global__ void k_bn(float* __restrict__ out, const float* __restrict__ gamma,
                     const float* __restrict__ beta) {
    __shared__ float ssc[OCH], sbi[OCH];
    if (threadIdx.x < OCH) {
        int o = threadIdx.x;
        float invN = 1.0f / ((float)Bb * NPIX);
        float m = g_bnsum[o] * invN;
        float v = g_bnsq[o] * invN - m * m;
        float sc = gamma[o] * rsqrtf(v + 1e-5f);
        ssc[o] = sc;
        sbi[o] = beta[o] - m * sc;
    }
    __syncthreads();
    size_t total = (size_t)Bb * OCH * NPIX;
    for (size_t i = (size_t)blockIdx.x * blockDim.x + threadIdx.x; i < total;
         i += (size_t)gridDim.x * blockDim.x) {
        int o = (int)((i / NPIX) & 31);
        float v = fmaf(out[i], ssc[o], sbi[o]);
        out[i] = fmaxf(v, 0.0f);
    }
}

// ---------------- launch ----------------
extern "C" void kernel_launch(void* const* d_in, const int* in_sizes, int n_in,
                              void* d_out, int out_size) {
    (void)in_sizes; (void)n_in; (void)out_size;
    const float* cen   = (const float*)d_in[0];
    const float* wq    = (const float*)d_in[1];
    const float* wk    = (const float*)d_in[2];
    const float* wv    = (const float*)d_in[3];
    const float* sum_w = (const float*)d_in[4];
    const float* w_out = (const float*)d_in[5];
    const float* gamma = (const float*)d_in[6];
    const float* beta  = (const float*)d_in[7];
    float* out = (float*)d_out;

    int dynsmem_out  = (Cc * 3 * W2 + OCH * SDIM) * (int)sizeof(float);
    int dynsmem_attn = 46096 * (int)sizeof(float);
    cudaFuncSetAttribute(k_out,  cudaFuncAttributeMaxDynamicSharedMemorySize, dynsmem_out);
    cudaFuncSetAttribute(k_attn, cudaFuncAttributeMaxDynamicSharedMemorySize, dynsmem_attn);

    k_prep<<<4, 256>>>(wq, wk, wv, sum_w);
    k_zero<<<1024, 256>>>();
    k_S<<<dim3(24, 4, 8), 288>>>(cen);
    k_mirror<<<32, 256>>>();
    k_attn<<<32, 512, dynsmem_attn>>>(w_out);
    k_out<<<dim3(48, 8), 256, dynsmem_out>>>(cen, out);
    k_bn<<<2048, 256>>>(out, gamma, beta);
}

// round 4
// speedup vs baseline: 1.1841x; 1.1841x over previous
#include <cuda_runtime.h>
#include <math.h>

#define Bb 8
#define Cc 16
#define WD 192
#define HT 192
#define NPIX (WD*HT)
#define Hh 4
#define HID 16
#define OCH 32
#define W2 214
#define SDIM 144

// ---------------- device scratch (no allocations allowed) ----------------
__device__ float g_Wq[Hh][HID][SDIM];
__device__ float g_Wk[Hh][128][SDIM];
__device__ float g_Wv[Hh][128][SDIM];
__device__ float g_S[Bb*Hh][SDIM*SDIM];
__device__ float g_W2[Bb][Hh][OCH][SDIM];
__device__ float g_bnsum[OCH];
__device__ float g_bnsq[OCH];

__constant__ int c_shift[4] = {1, 2, 4, 8};
__constant__ int c_off[8]   = {0, 1, 2, 5, 8, 7, 6, 3}; // position of the -1 tap per contrast kernel

// ---------------- kernel 1: fold blend kernels into effective conv weights ----------------
__global__ void k_prep(const float* __restrict__ wq, const float* __restrict__ wk,
                       const float* __restrict__ wv, const float* __restrict__ sum_w) {
    int h = blockIdx.x;
    int t = threadIdx.x;
    __shared__ float wcen[Cc][9];
    __shared__ float wsur[Cc][8][9];

    if (t < Cc * 9) {
        int c = t / 9, d = t % 9;
        float sw = sum_w[h * Cc + c];
        float su_f = (d == 4) ? 0.125f : (7.0f / 64.0f);
        float ce   = (d == 4) ? 1.0f : 0.0f;
        wcen[c][d] = su_f * (1.0f - sw) + ce * sw;
    }
    for (int idx = t; idx < Cc * 8 * 9; idx += 256) {
        int c = idx / 72;
        int k = (idx / 9) % 8;
        int d = idx % 9;
        float sw = sum_w[h * Cc + c];
        float delta = ((d == 4) ? 1.0f : 0.0f) + ((d == c_off[k]) ? -1.0f : 0.0f);
        float ce    = (d == 4) ? 1.0f : 0.0f;
        float k2w   = (delta - ce) * 1.125f + 0.125f;
        wsur[c][k][d] = delta * (1.0f - sw) + k2w * sw;
    }
    __syncthreads();

    for (int idx = t; idx < HID * SDIM; idx += 256) {
        int q = idx / SDIM, c = (idx % SDIM) / 9, d = idx % 9;
        g_Wq[h][q][c * 9 + d] = wq[(h * HID + q) * Cc + c] * wcen[c][d];
    }
    for (int idx = t; idx < 128 * SDIM; idx += 256) {
        int o = idx / SDIM, c = (idx % SDIM) / 9, d = idx % 9;
        float ak = 0.0f, av = 0.0f;
        #pragma unroll
        for (int k = 0; k < 8; k++) {
            float ws = wsur[c][k][d];
            ak = fmaf(wk[(h * 128 + o) * 128 + k * Cc + c], ws, ak);
            av = fmaf(wv[(h * 128 + o) * 128 + k * Cc + c], ws, av);
        }
        g_Wk[h][o][c * 9 + d] = ak;
        g_Wv[h][o][c * 9 + d] = av;
    }
}

// ---------------- kernel 2: zero scratch accumulators ----------------
__global__ void k_zero() {
    long total = (long)Bb * Hh * SDIM * SDIM;
    float* p = &g_S[0][0];
    for (long i = (long)blockIdx.x * 256 + threadIdx.x; i < total; i += (long)gridDim.x * 256)
        p[i] = 0.0f;
    if (blockIdx.x == 0 && threadIdx.x < OCH) {
        g_bnsum[threadIdx.x] = 0.0f;
        g_bnsq[threadIdx.x]  = 0.0f;
    }
}

// ---------------- kernel 3: S = X X^T, upper triangle only (symmetry) ----------------
// grid (24 x-groups of 8 rows, Hh, Bb), 272 threads:
//   threads 0..135   : tiles 0..135 (ti<=tj), y in [0,96)
//   threads 136..271 : tiles 0..135,           y in [96,192)
// Contiguous halves keep y uniform within (almost all) warps; tile index
// mostly shares ti across a 16-lane group so the a-row loads broadcast.
__global__ void __launch_bounds__(272, 2) k_S(const float* __restrict__ cen) {
    __shared__ float sm[Cc * 3 * W2];
    int xg = blockIdx.x, h = blockIdx.y, b = blockIdx.z;
    int s = c_shift[h];
    int t = threadIdx.x;

    int p = (t >= 136) ? (t - 136) : t;
    int ti = 0, rem = p;
    while (rem >= 16 - ti) { rem -= 16 - ti; ti++; }
    int tj = ti + rem;
    int ybeg = (t >= 136) ? 96 : 0;
    int yend = ybeg + 96;

    float acc[81];
    #pragma unroll
    for (int i = 0; i < 81; i++) acc[i] = 0.0f;

    const float* cb = cen + (size_t)b * Cc * NPIX;
    int plen = HT + 2 * s;

    for (int xr = 0; xr < 8; xr++) {
        int x = xg * 8 + xr;
        __syncthreads();
        for (int idx = t; idx < Cc * 3 * plen; idx += 272) {
            int c = idx / (3 * plen);
            int rm = idx - c * 3 * plen;
            int r = rm / plen;
            int pp = rm - r * plen;
            int xx = x + (r - 1) * s;
            int y = pp - s;
            float v = 0.0f;
            if (xx >= 0 && xx < WD && y >= 0 && y < HT)
                v = cb[((size_t)c * WD + xx) * HT + y];
            sm[c * (3 * W2) + r * W2 + pp] = v;
        }
        __syncthreads();

        const float* pa = sm + ti * (3 * W2);
        const float* pb = sm + tj * (3 * W2);
        #pragma unroll 2
        for (int y = ybeg; y < yend; y++) {
            float a[9];
            #pragma unroll
            for (int i = 0; i < 9; i++) a[i] = pa[(i / 3) * W2 + (i % 3) * s + y];
            #pragma unroll
            for (int j = 0; j < 9; j++) {
                float bv = pb[(j / 3) * W2 + (j % 3) * s + y];
                #pragma unroll
                for (int i = 0; i < 9; i++)
                    acc[i * 9 + j] = fmaf(a[i], bv, acc[i * 9 + j]);
            }
        }
    }

    {
        float* Sg = g_S[b * Hh + h];
        #pragma unroll
        for (int i = 0; i < 9; i++)
            #pragma unroll
            for (int j = 0; j < 9; j++)
                atomicAdd(&Sg[(ti * 9 + i) * SDIM + (tj * 9 + j)], acc[i * 9 + j]);
    }
}

// ---------------- kernel 3b: mirror upper triangle of S into lower ----------------
__global__ void k_mirror() {
    float* Sg = g_S[blockIdx.x];
    for (int idx = threadIdx.x; idx < SDIM * SDIM; idx += blockDim.x) {
        int r = idx / SDIM, c = idx - r * SDIM;
        if (r > c) Sg[idx] = Sg[c * SDIM + r];
    }
}

// ---------------- kernel 4: per (b,h) attention head from S (smem-resident) ----------------
// dyn smem layout (floats):
//   S_sm  [144 x 145]  @0        (20880)
//   Wk_sm [128 x 145]  @20880    (18560)   (overlaid by M[32x128] after softmax)
//   Wq_sm [16 x 144]   @39440    (2304)
//   T_sm  [16 x 144]   @41744    (2304)
//   G     [16 x 128]   @44048    (2048)    total 46096 floats = 184384 B
__global__ void __launch_bounds__(512) k_attn(const float* __restrict__ w_out) {
    extern __shared__ float pool[];
    float* S_sm  = pool;
    float* Wk_sm = pool + 20880;
    float* Wq_sm = pool + 39440;
    float* T_sm  = pool + 41744;
    float* G     = pool + 44048;
    float* M     = Wk_sm;          // overlay after Wk is consumed
    __shared__ float nq[16], nk[128], red[512];

    int bh = blockIdx.x;
    int b = bh >> 2, h = bh & 3;
    int t = threadIdx.x;
    const float* Sg = g_S[bh];

    for (int idx = t; idx < SDIM * SDIM; idx += 512) {
        int r = idx / SDIM, c = idx - r * SDIM;
        S_sm[r * 145 + c] = Sg[idx];
    }
    for (int idx = t; idx < 128 * SDIM; idx += 512) {
        int r = idx / SDIM, c = idx - r * SDIM;
        Wk_sm[r * 145 + c] = (&g_Wk[h][0][0])[idx];
    }
    for (int idx = t; idx < 16 * SDIM; idx += 512)
        Wq_sm[idx] = (&g_Wq[h][0][0])[idx];
    __syncthreads();

    // T = Wq * S
    for (int idx = t; idx < 16 * SDIM; idx += 512) {
        int q = idx / SDIM, i = idx - q * SDIM;
        float a = 0.0f;
        #pragma unroll 4
        for (int j = 0; j < SDIM; j++)
            a = fmaf(Wq_sm[q * SDIM + j], S_sm[j * 145 + i], a);
        T_sm[idx] = a;
    }
    __syncthreads();

    // ||Q_q||^2 = T_q . Wq_q
    if (t < 16) {
        float a = 0.0f;
        for (int i = 0; i < SDIM; i++)
            a = fmaf(T_sm[t * SDIM + i], Wq_sm[t * SDIM + i], a);
        nq[t] = fmaxf(sqrtf(fmaxf(a, 0.0f)), 1e-12f);
    }

    // G[q][k] = T_q . Wk_k
    for (int idx = t; idx < 2048; idx += 512) {
        int q = idx >> 7, k = idx & 127;
        float a = 0.0f;
        #pragma unroll 4
        for (int i = 0; i < SDIM; i++)
            a = fmaf(T_sm[q * SDIM + i], Wk_sm[k * 145 + i], a);
        G[idx] = a;
    }

    // ||K_k||^2 = Wk_k S Wk_k^T  (128 k x 4 row-groups of 36)
    {
        int k = t & 127, g = t >> 7;
        float a = 0.0f;
        for (int i = g * 36; i < g * 36 + 36; i++) {
            float rd = 0.0f;
            #pragma unroll 4
            for (int j = 0; j < SDIM; j++)
                rd = fmaf(S_sm[i * 145 + j], Wk_sm[k * 145 + j], rd);
            a = fmaf(Wk_sm[k * 145 + i], rd, a);
        }
        red[t] = a;
    }
    __syncthreads();
    if (t < 128) {
        float sum = red[t] + red[t + 128] + red[t + 256] + red[t + 384];
        nk[t] = fmaxf(sqrtf(fmaxf(sum, 0.0f)), 1e-12f);
    }
    __syncthreads();

    // score = G / (|Q||K| sqrt(N)); sqrt(36864) = 192
    for (int idx = t; idx < 2048; idx += 512) {
        int q = idx >> 7, k = idx & 127;
        G[idx] = G[idx] / (nq[q] * nk[k] * 192.0f);
    }
    __syncthreads();

    // instance norm over 16x128
    float lsum = 0.0f;
    for (int idx = t; idx < 2048; idx += 512) lsum += G[idx];
    red[t] = lsum; __syncthreads();
    for (int st = 256; st > 0; st >>= 1) { if (t < st) red[t] += red[t + st]; __syncthreads(); }
    float mean = red[0] * (1.0f / 2048.0f);
    __syncthreads();
    float lss = 0.0f;
    for (int idx = t; idx < 2048; idx += 512) { float d = G[idx] - mean; lss = fmaf(d, d, lss); }
    red[t] = lss; __syncthreads();
    for (int st = 256; st > 0; st >>= 1) { if (t < st) red[t] += red[t + st]; __syncthreads(); }
    float var = red[0] * (1.0f / 2048.0f);
    float iscale = rsqrtf(var + 1e-5f);
    __syncthreads();
    for (int idx = t; idx < 2048; idx += 512)
        G[idx] = (G[idx] - mean) * iscale;
    __syncthreads();

    // softmax over k per row (16 warps x 1 row)
    int wid = t >> 5, lane = t & 31;
    {
        int q = wid;
        float m = -1e30f;
        for (int k = lane; k < 128; k += 32) m = fmaxf(m, G[q * 128 + k]);
        #pragma unroll
        for (int o = 16; o > 0; o >>= 1) m = fmaxf(m, __shfl_xor_sync(0xffffffffu, m, o));
        float ssum = 0.0f;
        for (int k = lane; k < 128; k += 32) {
            float e = expf(G[q * 128 + k] - m);
            G[q * 128 + k] = e;
            ssum += e;
        }
        #pragma unroll
        for (int o = 16; o > 0; o >>= 1) ssum += __shfl_xor_sync(0xffffffffu, ssum, o);
        float inv = 1.0f / ssum;
        for (int k = lane; k < 128; k += 32) G[q * 128 + k] *= inv;
    }
    __syncthreads();

    // M[o][k] = sum_q w_out[o, h*16+q] attn[q][k]   (M overlays Wk_sm)
    float mv[8];
    {
        #pragma unroll
        for (int r = 0; r < 8; r++) {
            int idx = t + r * 512;
            int o = idx >> 7, k = idx & 127;
            float a = 0.0f;
            #pragma unroll
            for (int q = 0; q < 16; q++)
                a = fmaf(w_out[o * 64 + h * 16 + q], G[q * 128 + k], a);
            mv[r] = a;
        }
    }
    __syncthreads();   // all reads of Wk_sm done before overlay write
    #pragma unroll
    for (int r = 0; r < 8; r++) M[t + r * 512] = mv[r];
    __syncthreads();

    // Weff2[o][i] = sum_k M[o][k] Wv[k][i]
    for (int idx = t; idx < OCH * SDIM; idx += 512) {
        int o = idx / SDIM, i = idx - o * SDIM;
        float a = 0.0f;
        #pragma unroll 4
        for (int k = 0; k < 128; k++)
            a = fmaf(M[o * 128 + k], g_Wv[h][k][i], a);
        g_W2[b][h][o][i] = a;
    }
}

// ---------------- kernel 5: fused output conv (4 dilated 3x3 convs) + BN stats ----------------
// grid (48 x-groups of 4 rows, Bb), 256 threads = 8 warps (o-groups of 4) x 32 lanes (y-groups of 6)
__global__ void __launch_bounds__(256) k_out(const float* __restrict__ cen, float* __restrict__ out) {
    extern __shared__ float dsm[];
    float* insm = dsm;                 // Cc*3*W2 = 10272 floats
    float* W2sm = dsm + Cc * 3 * W2;   // OCH*SDIM = 4608 floats

    int xg = blockIdx.x, b = blockIdx.y;
    int t = threadIdx.x;
    int ty = t & 31, to = t >> 5;
    const float* cb = cen + (size_t)b * Cc * NPIX;

    for (int xr = 0; xr < 4; xr++) {
        int x = xg * 4 + xr;
        float acc[4][6];
        #pragma unroll
        for (int oo = 0; oo < 4; oo++)
            #pragma unroll
            for (int j = 0; j < 6; j++) acc[oo][j] = 0.0f;

        for (int h = 0; h < Hh; h++) {
            int s = c_shift[h];
            int plen = HT + 2 * s;
            __syncthreads();
            for (int idx = t; idx < Cc * 3 * plen; idx += 256) {
                int c = idx / (3 * plen);
                int rem = idx - c * 3 * plen;
                int r = rem / plen;
                int p = rem - r * plen;
                int xx = x + (r - 1) * s;
                int y = p - s;
                float v = 0.0f;
                if (xx >= 0 && xx < WD && y >= 0 && y < HT)
                    v = cb[((size_t)c * WD + xx) * HT + y];
                insm[c * (3 * W2) + r * W2 + p] = v;
            }
            for (int idx = t; idx < OCH * SDIM; idx += 256)
                W2sm[idx] = (&g_W2[b][h][0][0])[idx];
            __syncthreads();

            int ybase = ty * 6;
            #pragma unroll 1
            for (int c = 0; c < Cc; c++) {
                const float* pc = insm + c * (3 * W2);
                #pragma unroll
                for (int d = 0; d < 9; d++) {
                    const float* px = pc + (d / 3) * W2 + (d % 3) * s + ybase;
                    float w0 = W2sm[(to * 4 + 0) * SDIM + c * 9 + d];
                    float w1 = W2sm[(to * 4 + 1) * SDIM + c * 9 + d];
                    float w2 = W2sm[(to * 4 + 2) * SDIM + c * 9 + d];
                    float w3 = W2sm[(to * 4 + 3) * SDIM + c * 9 + d];
                    #pragma unroll
                    for (int j = 0; j < 6; j++) {
                        float xv = px[j];
                        acc[0][j] = fmaf(w0, xv, acc[0][j]);
                        acc[1][j] = fmaf(w1, xv, acc[1][j]);
                        acc[2][j] = fmaf(w2, xv, acc[2][j]);
                        acc[3][j] = fmaf(w3, xv, acc[3][j]);
                    }
                }
            }
        }

        // write raw y + accumulate BN stats
        #pragma unroll
        for (int oo = 0; oo < 4; oo++) {
            int o = to * 4 + oo;
            float s1 = 0.0f, s2 = 0.0f;
            float* op = out + (((size_t)b * OCH + o) * WD + x) * HT + ty * 6;
            #pragma unroll
            for (int j = 0; j < 6; j++) {
                float v = acc[oo][j];
                op[j] = v;
                s1 += v;
                s2 = fmaf(v, v, s2);
            }
            #pragma unroll
            for (int off2 = 16; off2 > 0; off2 >>= 1) {
                s1 += __shfl_xor_sync(0xffffffffu, s1, off2);
                s2 += __shfl_xor_sync(0xffffffffu, s2, off2);
            }
            if (ty == 0) {
                atomicAdd(&g_bnsum[o], s1);
                atomicAdd(&g_bnsq[o], s2);
            }
        }
    }
}

// ---------------- kernel 6: batchnorm (train stats) + ReLU, in place ----------------
__global__ void k_bn(float* __restrict__ out, const float* __restrict__ gamma,
                     const float* __restrict__ beta) {
    __shared__ float ssc[OCH], sbi[OCH];
    if (threadIdx.x < OCH) {
        int o = threadIdx.x;
        float invN = 1.0f / ((float)Bb * NPIX);
        float m = g_bnsum[o] * invN;
        float v = g_bnsq[o] * invN - m * m;
        float sc = gamma[o] * rsqrtf(v + 1e-5f);
        ssc[o] = sc;
        sbi[o] = beta[o] - m * sc;
    }
    __syncthreads();
    size_t total = (size_t)Bb * OCH * NPIX;
    for (size_t i = (size_t)blockIdx.x * blockDim.x + threadIdx.x; i < total;
         i += (size_t)gridDim.x * blockDim.x) {
        int o = (int)((i / NPIX) & 31);
        float v = fmaf(out[i], ssc[o], sbi[o]);
        out[i] = fmaxf(v, 0.0f);
    }
}

// ---------------- launch ----------------
extern "C" void kernel_launch(void* const* d_in, const int* in_sizes, int n_in,
                              void* d_out, int out_size) {
    (void)in_sizes; (void)n_in; (void)out_size;
    const float* cen   = (const float*)d_in[0];
    const float* wq    = (const float*)d_in[1];
    const float* wk    = (const float*)d_in[2];
    const float* wv    = (const float*)d_in[3];
    const float* sum_w = (const float*)d_in[4];
    const float* w_out = (const float*)d_in[5];
    const float* gamma = (const float*)d_in[6];
    const float* beta  = (const float*)d_in[7];
    float* out = (float*)d_out;

    int dynsmem_out  = (Cc * 3 * W2 + OCH * SDIM) * (int)sizeof(float);
    int dynsmem_attn = 46096 * (int)sizeof(float);
    cudaFuncSetAttribute(k_out,  cudaFuncAttributeMaxDynamicSharedMemorySize, dynsmem_out);
    cudaFuncSetAttribute(k_attn, cudaFuncAttributeMaxDynamicSharedMemorySize, dynsmem_attn);

    k_prep<<<4, 256>>>(wq, wk, wv, sum_w);
    k_zero<<<1024, 256>>>();
    k_S<<<dim3(24, 4, 8), 272>>>(cen);
    k_mirror<<<32, 256>>>();
    k_attn<<<32, 512, dynsmem_attn>>>(w_out);
    k_out<<<dim3(48, 8), 256, dynsmem_out>>>(cen, out);
    k_bn<<<2048, 256>>>(out, gamma, beta);
}

// round 5
// speedup vs baseline: 1.1913x; 1.0060x over previous
#include <cuda_runtime.h>
#include <math.h>

#define Bb 8
#define Cc 16
#define WD 192
#define HT 192
#define NPIX (WD*HT)
#define Hh 4
#define HID 16
#define OCH 32
#define W2 214
#define SDIM 144

typedef unsigned long long ull;

// ---------------- packed f32x2 helpers ----------------
__device__ __forceinline__ ull pk2(float lo, float hi) {
    ull u;
    asm("mov.b64 %0, {%1, %2};" : "=l"(u) : "f"(lo), "f"(hi));
    return u;
}
__device__ __forceinline__ void upk2(ull u, float& lo, float& hi) {
    asm("mov.b64 {%0, %1}, %2;" : "=f"(lo), "=f"(hi) : "l"(u));
}
__device__ __forceinline__ ull ffma2(ull a, ull b, ull c) {
    ull d;
    asm("fma.rn.f32x2 %0, %1, %2, %3;" : "=l"(d) : "l"(a), "l"(b), "l"(c));
    return d;
}

// ---------------- device scratch (no allocations allowed) ----------------
__device__ float g_Wq[Hh][HID][SDIM];
__device__ float g_Wk[Hh][128][SDIM];
__device__ float g_Wv[Hh][128][SDIM];
__device__ float g_S[Bb*Hh][SDIM*SDIM];
__device__ float g_W2[Bb][Hh][OCH][SDIM];
__device__ float g_bnsum[OCH];
__device__ float g_bnsq[OCH];

__constant__ int c_shift[4] = {1, 2, 4, 8};
__constant__ int c_off[8]   = {0, 1, 2, 5, 8, 7, 6, 3}; // position of the -1 tap per contrast kernel

// ---------------- kernel 1: fold blend kernels into effective conv weights ----------------
__global__ void k_prep(const float* __restrict__ wq, const float* __restrict__ wk,
                       const float* __restrict__ wv, const float* __restrict__ sum_w) {
    int h = blockIdx.x;
    int t = threadIdx.x;
    __shared__ float wcen[Cc][9];
    __shared__ float wsur[Cc][8][9];

    if (t < Cc * 9) {
        int c = t / 9, d = t % 9;
        float sw = sum_w[h * Cc + c];
        float su_f = (d == 4) ? 0.125f : (7.0f / 64.0f);
        float ce   = (d == 4) ? 1.0f : 0.0f;
        wcen[c][d] = su_f * (1.0f - sw) + ce * sw;
    }
    for (int idx = t; idx < Cc * 8 * 9; idx += 256) {
        int c = idx / 72;
        int k = (idx / 9) % 8;
        int d = idx % 9;
        float sw = sum_w[h * Cc + c];
        float delta = ((d == 4) ? 1.0f : 0.0f) + ((d == c_off[k]) ? -1.0f : 0.0f);
        float ce    = (d == 4) ? 1.0f : 0.0f;
        float k2w   = (delta - ce) * 1.125f + 0.125f;
        wsur[c][k][d] = delta * (1.0f - sw) + k2w * sw;
    }
    __syncthreads();

    for (int idx = t; idx < HID * SDIM; idx += 256) {
        int q = idx / SDIM, c = (idx % SDIM) / 9, d = idx % 9;
        g_Wq[h][q][c * 9 + d] = wq[(h * HID + q) * Cc + c] * wcen[c][d];
    }
    for (int idx = t; idx < 128 * SDIM; idx += 256) {
        int o = idx / SDIM, c = (idx % SDIM) / 9, d = idx % 9;
        float ak = 0.0f, av = 0.0f;
        #pragma unroll
        for (int k = 0; k < 8; k++) {
            float ws = wsur[c][k][d];
            ak = fmaf(wk[(h * 128 + o) * 128 + k * Cc + c], ws, ak);
            av = fmaf(wv[(h * 128 + o) * 128 + k * Cc + c], ws, av);
        }
        g_Wk[h][o][c * 9 + d] = ak;
        g_Wv[h][o][c * 9 + d] = av;
    }
}

// ---------------- kernel 2: zero scratch accumulators ----------------
__global__ void k_zero() {
    long total = (long)Bb * Hh * SDIM * SDIM;
    float* p = &g_S[0][0];
    for (long i = (long)blockIdx.x * 256 + threadIdx.x; i < total; i += (long)gridDim.x * 256)
        p[i] = 0.0f;
    if (blockIdx.x == 0 && threadIdx.x < OCH) {
        g_bnsum[threadIdx.x] = 0.0f;
        g_bnsq[threadIdx.x]  = 0.0f;
    }
}

// ---------------- kernel 3: S = X X^T (full, f32x2 packed over y-pairs) ----------------
// 576 threads: ti = t/36 (16 a-tiles of 9 rows = one channel), tj = t%36 (36 b-tiles of 4 rows).
// Each thread: 9x4 output tile, accumulators packed as f32x2 over (y, y+1).
template<int S>
__device__ __forceinline__ void kS_body(const float* __restrict__ cb, float* __restrict__ Sg,
                                        float* sm, int xg, int t) {
    constexpr int plen = HT + 2 * S;
    int ti = t / 36;
    int tj = t - ti * 36;

    int boff[4];
    #pragma unroll
    for (int j = 0; j < 4; j++) {
        int r = 4 * tj + j;
        int c = r / 9, d = r - c * 9;
        boff[j] = c * (3 * W2) + (d / 3) * W2 + (d % 3) * S;
    }
    const float* pa = sm + ti * (3 * W2);

    ull acc[36];
    #pragma unroll
    for (int i = 0; i < 36; i++) acc[i] = 0ull;

    for (int xr = 0; xr < 8; xr++) {
        int x = xg * 8 + xr;
        __syncthreads();
        for (int idx = t; idx < Cc * 3 * plen; idx += 576) {
            int c = idx / (3 * plen);
            int rm = idx - c * 3 * plen;
            int r = rm / plen;
            int pp = rm - r * plen;
            int xx = x + (r - 1) * S;
            int y = pp - S;
            float v = 0.0f;
            if (xx >= 0 && xx < WD && y >= 0 && y < HT)
                v = cb[((size_t)c * WD + xx) * HT + y];
            sm[c * (3 * W2) + r * W2 + pp] = v;
        }
        __syncthreads();

        #pragma unroll 2
        for (int yp = 0; yp < 96; yp++) {
            int y = 2 * yp;
            ull b2[4];
            #pragma unroll
            for (int j = 0; j < 4; j++) {
                if constexpr ((S & 1) == 0)
                    b2[j] = *(const ull*)(sm + boff[j] + y);   // 8B aligned: all terms even
                else
                    b2[j] = pk2(sm[boff[j] + y], sm[boff[j] + y + 1]);
            }
            #pragma unroll
            for (int i = 0; i < 9; i++) {
                const int offi = (i / 3) * W2 + (i % 3) * S;
                ull a2;
                if constexpr ((S & 1) == 0)
                    a2 = *(const ull*)(pa + offi + y);
                else
                    a2 = pk2(pa[offi + y], pa[offi + y + 1]);
                #pragma unroll
                for (int j = 0; j < 4; j++)
                    acc[i * 4 + j] = ffma2(a2, b2[j], acc[i * 4 + j]);
            }
        }
    }

    #pragma unroll
    for (int i = 0; i < 9; i++)
        #pragma unroll
        for (int j = 0; j < 4; j++) {
            float lo, hi;
            upk2(acc[i * 4 + j], lo, hi);
            atomicAdd(&Sg[(9 * ti + i) * SDIM + (4 * tj + j)], lo + hi);
        }
}

__global__ void __launch_bounds__(576, 1) k_S(const float* __restrict__ cen) {
    __shared__ float sm[Cc * 3 * W2];
    int xg = blockIdx.x, h = blockIdx.y, b = blockIdx.z;
    const float* cb = cen + (size_t)b * Cc * NPIX;
    float* Sg = g_S[b * Hh + h];
    int t = threadIdx.x;
    switch (h) {
        case 0: kS_body<1>(cb, Sg, sm, xg, t); break;
        case 1: kS_body<2>(cb, Sg, sm, xg, t); break;
        case 2: kS_body<4>(cb, Sg, sm, xg, t); break;
        default: kS_body<8>(cb, Sg, sm, xg, t); break;
    }
}

// ---------------- kernel 4: per (b,h) attention head from S (smem-resident) ----------------
// dyn smem layout (floats):
//   S_sm  [144 x 145]  @0        (20880)
//   Wk_sm [128 x 145]  @20880    (18560)   (overlaid by M[32x128] after softmax)
//   Wq_sm [16 x 144]   @39440    (2304)
//   T_sm  [16 x 144]   @41744    (2304)
//   G     [16 x 128]   @44048    (2048)    total 46096 floats = 184384 B
__global__ void __launch_bounds__(512) k_attn(const float* __restrict__ w_out) {
    extern __shared__ float pool[];
    float* S_sm  = pool;
    float* Wk_sm = pool + 20880;
    float* Wq_sm = pool + 39440;
    float* T_sm  = pool + 41744;
    float* G     = pool + 44048;
    float* M     = Wk_sm;          // overlay after Wk is consumed
    __shared__ float nq[16], nk[128], red[512];

    int bh = blockIdx.x;
    int b = bh >> 2, h = bh & 3;
    int t = threadIdx.x;
    const float* Sg = g_S[bh];

    for (int idx = t; idx < SDIM * SDIM; idx += 512) {
        int r = idx / SDIM, c = idx - r * SDIM;
        S_sm[r * 145 + c] = Sg[idx];
    }
    for (int idx = t; idx < 128 * SDIM; idx += 512) {
        int r = idx / SDIM, c = idx - r * SDIM;
        Wk_sm[r * 145 + c] = (&g_Wk[h][0][0])[idx];
    }
    for (int idx = t; idx < 16 * SDIM; idx += 512)
        Wq_sm[idx] = (&g_Wq[h][0][0])[idx];
    __syncthreads();

    // T = Wq * S
    for (int idx = t; idx < 16 * SDIM; idx += 512) {
        int q = idx / SDIM, i = idx - q * SDIM;
        float a = 0.0f;
        #pragma unroll 4
        for (int j = 0; j < SDIM; j++)
            a = fmaf(Wq_sm[q * SDIM + j], S_sm[j * 145 + i], a);
        T_sm[idx] = a;
    }
    __syncthreads();

    // ||Q_q||^2 = T_q . Wq_q
    if (t < 16) {
        float a = 0.0f;
        for (int i = 0; i < SDIM; i++)
            a = fmaf(T_sm[t * SDIM + i], Wq_sm[t * SDIM + i], a);
        nq[t] = fmaxf(sqrtf(fmaxf(a, 0.0f)), 1e-12f);
    }

    // G[q][k] = T_q . Wk_k
    for (int idx = t; idx < 2048; idx += 512) {
        int q = idx >> 7, k = idx & 127;
        float a = 0.0f;
        #pragma unroll 4
        for (int i = 0; i < SDIM; i++)
            a = fmaf(T_sm[q * SDIM + i], Wk_sm[k * 145 + i], a);
        G[idx] = a;
    }

    // ||K_k||^2 = Wk_k S Wk_k^T  (128 k x 4 row-groups of 36)
    {
        int k = t & 127, g = t >> 7;
        float a = 0.0f;
        for (int i = g * 36; i < g * 36 + 36; i++) {
            float rd = 0.0f;
            #pragma unroll 4
            for (int j = 0; j < SDIM; j++)
                rd = fmaf(S_sm[i * 145 + j], Wk_sm[k * 145 + j], rd);
            a = fmaf(Wk_sm[k * 145 + i], rd, a);
        }
        red[t] = a;
    }
    __syncthreads();
    if (t < 128) {
        float sum = red[t] + red[t + 128] + red[t + 256] + red[t + 384];
        nk[t] = fmaxf(sqrtf(fmaxf(sum, 0.0f)), 1e-12f);
    }
    __syncthreads();

    // score = G / (|Q||K| sqrt(N)); sqrt(36864) = 192
    for (int idx = t; idx < 2048; idx += 512) {
        int q = idx >> 7, k = idx & 127;
        G[idx] = G[idx] / (nq[q] * nk[k] * 192.0f);
    }
    __syncthreads();

    // instance norm over 16x128
    float lsum = 0.0f;
    for (int idx = t; idx < 2048; idx += 512) lsum += G[idx];
    red[t] = lsum; __syncthreads();
    for (int st = 256; st > 0; st >>= 1) { if (t < st) red[t] += red[t + st]; __syncthreads(); }
    float mean = red[0] * (1.0f / 2048.0f);
    __syncthreads();
    float lss = 0.0f;
    for (int idx = t; idx < 2048; idx += 512) { float d = G[idx] - mean; lss = fmaf(d, d, lss); }
    red[t] = lss; __syncthreads();
    for (int st = 256; st > 0; st >>= 1) { if (t < st) red[t] += red[t + st]; __syncthreads(); }
    float var = red[0] * (1.0f / 2048.0f);
    float iscale = rsqrtf(var + 1e-5f);
    __syncthreads();
    for (int idx = t; idx < 2048; idx += 512)
        G[idx] = (G[idx] - mean) * iscale;
    __syncthreads();

    // softmax over k per row (16 warps x 1 row)
    int wid = t >> 5, lane = t & 31;
    {
        int q = wid;
        float m = -1e30f;
        for (int k = lane; k < 128; k += 32) m = fmaxf(m, G[q * 128 + k]);
        #pragma unroll
        for (int o = 16; o > 0; o >>= 1) m = fmaxf(m, __shfl_xor_sync(0xffffffffu, m, o));
        float ssum = 0.0f;
        for (int k = lane; k < 128; k += 32) {
            float e = expf(G[q * 128 + k] - m);
            G[q * 128 + k] = e;
            ssum += e;
        }
        #pragma unroll
        for (int o = 16; o > 0; o >>= 1) ssum += __shfl_xor_sync(0xffffffffu, ssum, o);
        float inv = 1.0f / ssum;
        for (int k = lane; k < 128; k += 32) G[q * 128 + k] *= inv;
    }
    __syncthreads();

    // M[o][k] = sum_q w_out[o, h*16+q] attn[q][k]   (M overlays Wk_sm)
    float mv[8];
    {
        #pragma unroll
        for (int r = 0; r < 8; r++) {
            int idx = t + r * 512;
            int o = idx >> 7, k = idx & 127;
            float a = 0.0f;
            #pragma unroll
            for (int q = 0; q < 16; q++)
                a = fmaf(w_out[o * 64 + h * 16 + q], G[q * 128 + k], a);
            mv[r] = a;
        }
    }
    __syncthreads();   // all reads of Wk_sm done before overlay write
    #pragma unroll
    for (int r = 0; r < 8; r++) M[t + r * 512] = mv[r];
    __syncthreads();

    // Weff2[o][i] = sum_k M[o][k] Wv[k][i]
    for (int idx = t; idx < OCH * SDIM; idx += 512) {
        int o = idx / SDIM, i = idx - o * SDIM;
        float a = 0.0f;
        #pragma unroll 4
        for (int k = 0; k < 128; k++)
            a = fmaf(M[o * 128 + k], g_Wv[h][k][i], a);
        g_W2[b][h][o][i] = a;
    }
}

// ---------------- kernel 5: fused output conv (4 dilated 3x3 convs, f32x2) + BN stats ----------------
// grid (48 x-groups of 4 rows, Bb), 256 threads = 8 warps (o-groups of 4) x 32 lanes (y-groups of 6)
__global__ void __launch_bounds__(256) k_out(const float* __restrict__ cen, float* __restrict__ out) {
    extern __shared__ float dsm[];
    float* insm = dsm;                 // Cc*3*W2 = 10272 floats
    float* W2sm = dsm + Cc * 3 * W2;   // OCH*SDIM = 4608 floats

    int xg = blockIdx.x, b = blockIdx.y;
    int t = threadIdx.x;
    int ty = t & 31, to = t >> 5;
    const float* cb = cen + (size_t)b * Cc * NPIX;

    for (int xr = 0; xr < 4; xr++) {
        int x = xg * 4 + xr;
        ull acc2[4][3];
        #pragma unroll
        for (int oo = 0; oo < 4; oo++)
            #pragma unroll
            for (int j = 0; j < 3; j++) acc2[oo][j] = 0ull;

        for (int h = 0; h < Hh; h++) {
            int s = c_shift[h];
            int plen = HT + 2 * s;
            __syncthreads();
            for (int idx = t; idx < Cc * 3 * plen; idx += 256) {
                int c = idx / (3 * plen);
                int rem = idx - c * 3 * plen;
                int r = rem / plen;
                int p = rem - r * plen;
                int xx = x + (r - 1) * s;
                int y = p - s;
                float v = 0.0f;
                if (xx >= 0 && xx < WD && y >= 0 && y < HT)
                    v = cb[((size_t)c * WD + xx) * HT + y];
                insm[c * (3 * W2) + r * W2 + p] = v;
            }
            for (int idx = t; idx < OCH * SDIM; idx += 256)
                W2sm[idx] = (&g_W2[b][h][0][0])[idx];
            __syncthreads();

            int ybase = ty * 6;
            #pragma unroll 1
            for (int c = 0; c < Cc; c++) {
                const float* pc = insm + c * (3 * W2);
                #pragma unroll
                for (int d = 0; d < 9; d++) {
                    const float* px = pc + (d / 3) * W2 + (d % 3) * s + ybase;
                    float w0 = W2sm[(to * 4 + 0) * SDIM + c * 9 + d];
                    float w1 = W2sm[(to * 4 + 1) * SDIM + c * 9 + d];
                    float w2 = W2sm[(to * 4 + 2) * SDIM + c * 9 + d];
                    float w3 = W2sm[(to * 4 + 3) * SDIM + c * 9 + d];
                    ull w0p = pk2(w0, w0), w1p = pk2(w1, w1);
                    ull w2p = pk2(w2, w2), w3p = pk2(w3, w3);
                    #pragma unroll
                    for (int j = 0; j < 3; j++) {
                        ull xv = pk2(px[2 * j], px[2 * j + 1]);
                        acc2[0][j] = ffma2(w0p, xv, acc2[0][j]);
                        acc2[1][j] = ffma2(w1p, xv, acc2[1][j]);
                        acc2[2][j] = ffma2(w2p, xv, acc2[2][j]);
                        acc2[3][j] = ffma2(w3p, xv, acc2[3][j]);
                    }
                }
            }
        }

        // write raw y + accumulate BN stats
        #pragma unroll
        for (int oo = 0; oo < 4; oo++) {
            int o = to * 4 + oo;
            float s1 = 0.0f, s2 = 0.0f;
            float* op = out + (((size_t)b * OCH + o) * WD + x) * HT + ty * 6;
            #pragma unroll
            for (int j = 0; j < 3; j++) {
                float lo, hi;
                upk2(acc2[oo][j], lo, hi);
                op[2 * j]     = lo;
                op[2 * j + 1] = hi;
                s1 += lo + hi;
                s2 = fmaf(lo, lo, s2);
                s2 = fmaf(hi, hi, s2);
            }
            #pragma unroll
            for (int off2 = 16; off2 > 0; off2 >>= 1) {
                s1 += __shfl_xor_sync(0xffffffffu, s1, off2);
                s2 += __shfl_xor_sync(0xffffffffu, s2, off2);
            }
            if (ty == 0) {
                atomicAdd(&g_bnsum[o], s1);
                atomicAdd(&g_bnsq[o], s2);
            }
        }
    }
}

// ---------------- kernel 6: batchnorm (train stats) + ReLU, in place ----------------
__global__ void k_bn(float* __restrict__ out, const float* __restrict__ gamma,
                     const float* __restrict__ beta) {
    __shared__ float ssc[OCH], sbi[OCH];
    if (threadIdx.x < OCH) {
        int o = threadIdx.x;
        float invN = 1.0f / ((float)Bb * NPIX);
        float m = g_bnsum[o] * invN;
        float v = g_bnsq[o] * invN - m * m;
        float sc = gamma[o] * rsqrtf(v + 1e-5f);
        ssc[o] = sc;
        sbi[o] = beta[o] - m * sc;
    }
    __syncthreads();
    size_t total = (size_t)Bb * OCH * NPIX;
    for (size_t i = (size_t)blockIdx.x * blockDim.x + threadIdx.x; i < total;
         i += (size_t)gridDim.x * blockDim.x) {
        int o = (int)((i / NPIX) & 31);
        float v = fmaf(out[i], ssc[o], sbi[o]);
        out[i] = fmaxf(v, 0.0f);
    }
}

// ---------------- launch ----------------
extern "C" void kernel_launch(void* const* d_in, const int* in_sizes, int n_in,
                              void* d_out, int out_size) {
    (void)in_sizes; (void)n_in; (void)out_size;
    const float* cen   = (const float*)d_in[0];
    const float* wq    = (const float*)d_in[1];
    const float* wk    = (const float*)d_in[2];
    const float* wv    = (const float*)d_in[3];
    const float* sum_w = (const float*)d_in[4];
    const float* w_out = (const float*)d_in[5];
    const float* gamma = (const float*)d_in[6];
    const float* beta  = (const float*)d_in[7];
    float* out = (float*)d_out;

    int dynsmem_out  = (Cc * 3 * W2 + OCH * SDIM) * (int)sizeof(float);
    int dynsmem_attn = 46096 * (int)sizeof(float);
    cudaFuncSetAttribute(k_out,  cudaFuncAttributeMaxDynamicSharedMemorySize, dynsmem_out);
    cudaFuncSetAttribute(k_attn, cudaFuncAttributeMaxDynamicSharedMemorySize, dynsmem_attn);

    k_prep<<<4, 256>>>(wq, wk, wv, sum_w);
    k_zero<<<1024, 256>>>();
    k_S<<<dim3(24, 4, 8), 576>>>(cen);
    k_attn<<<32, 512, dynsmem_attn>>>(w_out);
    k_out<<<dim3(48, 8), 256, dynsmem_out>>>(cen, out);
    k_bn<<<2048, 256>>>(out, gamma, beta);
}

// round 6
// speedup vs baseline: 1.4034x; 1.1781x over previous
#include <cuda_runtime.h>
#include <math.h>

#define Bb 8
#define Cc 16
#define WD 192
#define HT 192
#define NPIX (WD*HT)
#define Hh 4
#define HID 16
#define OCH 32
#define W2 214
#define SDIM 144

typedef unsigned long long ull;

// ---------------- packed f32x2 helpers ----------------
__device__ __forceinline__ ull pk2(float lo, float hi) {
    ull u;
    asm("mov.b64 %0, {%1, %2};" : "=l"(u) : "f"(lo), "f"(hi));
    return u;
}
__device__ __forceinline__ void upk2(ull u, float& lo, float& hi) {
    asm("mov.b64 {%0, %1}, %2;" : "=f"(lo), "=f"(hi) : "l"(u));
}
__device__ __forceinline__ ull ffma2(ull a, ull b, ull c) {
    ull d;
    asm("fma.rn.f32x2 %0, %1, %2, %3;" : "=l"(d) : "l"(a), "l"(b), "l"(c));
    return d;
}

// ---------------- device scratch (no allocations allowed) ----------------
__device__ float g_Wq[Hh][HID][SDIM];
__device__ float g_Wk[Hh][128][SDIM];
__device__ float g_Wv[Hh][128][SDIM];
__device__ float g_S[Bb*Hh][SDIM*SDIM];
__device__ float g_W2[Bb][Hh][OCH][SDIM];
__device__ float g_bnsum[OCH];
__device__ float g_bnsq[OCH];

__constant__ int c_shift[4] = {1, 2, 4, 8};
__constant__ int c_off[8]   = {0, 1, 2, 5, 8, 7, 6, 3}; // position of the -1 tap per contrast kernel

// ---------------- kernel 1: fold blend kernels into effective conv weights ----------------
__global__ void k_prep(const float* __restrict__ wq, const float* __restrict__ wk,
                       const float* __restrict__ wv, const float* __restrict__ sum_w) {
    int h = blockIdx.x;
    int t = threadIdx.x;
    __shared__ float wcen[Cc][9];
    __shared__ float wsur[Cc][8][9];

    if (t < Cc * 9) {
        int c = t / 9, d = t % 9;
        float sw = sum_w[h * Cc + c];
        float su_f = (d == 4) ? 0.125f : (7.0f / 64.0f);
        float ce   = (d == 4) ? 1.0f : 0.0f;
        wcen[c][d] = su_f * (1.0f - sw) + ce * sw;
    }
    for (int idx = t; idx < Cc * 8 * 9; idx += 256) {
        int c = idx / 72;
        int k = (idx / 9) % 8;
        int d = idx % 9;
        float sw = sum_w[h * Cc + c];
        float delta = ((d == 4) ? 1.0f : 0.0f) + ((d == c_off[k]) ? -1.0f : 0.0f);
        float ce    = (d == 4) ? 1.0f : 0.0f;
        float k2w   = (delta - ce) * 1.125f + 0.125f;
        wsur[c][k][d] = delta * (1.0f - sw) + k2w * sw;
    }
    __syncthreads();

    for (int idx = t; idx < HID * SDIM; idx += 256) {
        int q = idx / SDIM, c = (idx % SDIM) / 9, d = idx % 9;
        g_Wq[h][q][c * 9 + d] = wq[(h * HID + q) * Cc + c] * wcen[c][d];
    }
    for (int idx = t; idx < 128 * SDIM; idx += 256) {
        int o = idx / SDIM, c = (idx % SDIM) / 9, d = idx % 9;
        float ak = 0.0f, av = 0.0f;
        #pragma unroll
        for (int k = 0; k < 8; k++) {
            float ws = wsur[c][k][d];
            ak = fmaf(wk[(h * 128 + o) * 128 + k * Cc + c], ws, ak);
            av = fmaf(wv[(h * 128 + o) * 128 + k * Cc + c], ws, av);
        }
        g_Wk[h][o][c * 9 + d] = ak;
        g_Wv[h][o][c * 9 + d] = av;
    }
}

// ---------------- kernel 2: zero scratch accumulators ----------------
__global__ void k_zero() {
    long total = (long)Bb * Hh * SDIM * SDIM;
    float* p = &g_S[0][0];
    for (long i = (long)blockIdx.x * 256 + threadIdx.x; i < total; i += (long)gridDim.x * 256)
        p[i] = 0.0f;
    if (blockIdx.x == 0 && threadIdx.x < OCH) {
        g_bnsum[threadIdx.x] = 0.0f;
        g_bnsq[threadIdx.x]  = 0.0f;
    }
}

// ---------------- kernel 3: S = X X^T  (144x144 per (b,h)) — R1 proven version ----------------
// grid (24 x-groups of 8 rows, Hh, Bb), 256 threads as 16x16, each computes a 9x9 tile of S.
__global__ void __launch_bounds__(256, 2) k_S(const float* __restrict__ cen) {
    __shared__ float sm[Cc * 3 * W2];
    int xg = blockIdx.x, h = blockIdx.y, b = blockIdx.z;
    int s = c_shift[h];
    int t = threadIdx.x, ti = t & 15, tj = t >> 4;

    float acc[81];
    #pragma unroll
    for (int i = 0; i < 81; i++) acc[i] = 0.0f;

    const float* cb = cen + (size_t)b * Cc * NPIX;
    int plen = HT + 2 * s;

    for (int xr = 0; xr < 8; xr++) {
        int x = xg * 8 + xr;
        __syncthreads();
        for (int idx = t; idx < Cc * 3 * plen; idx += 256) {
            int c = idx / (3 * plen);
            int rem = idx - c * 3 * plen;
            int r = rem / plen;
            int p = rem - r * plen;
            int xx = x + (r - 1) * s;
            int y = p - s;
            float v = 0.0f;
            if (xx >= 0 && xx < WD && y >= 0 && y < HT)
                v = cb[((size_t)c * WD + xx) * HT + y];
            sm[c * (3 * W2) + r * W2 + p] = v;
        }
        __syncthreads();

        const float* pa = sm + ti * (3 * W2);
        const float* pb = sm + tj * (3 * W2);
        #pragma unroll 4
        for (int y = 0; y < HT; y++) {
            float a[9], bbv[9];
            #pragma unroll
            for (int i = 0; i < 9; i++) a[i] = pa[(i / 3) * W2 + (i % 3) * s + y];
            #pragma unroll
            for (int j = 0; j < 9; j++) bbv[j] = pb[(j / 3) * W2 + (j % 3) * s + y];
            #pragma unroll
            for (int i = 0; i < 9; i++)
                #pragma unroll
                for (int j = 0; j < 9; j++)
                    acc[i * 9 + j] = fmaf(a[i], bbv[j], acc[i * 9 + j]);
        }
    }

    float* Sg = g_S[b * Hh + h];
    #pragma unroll
    for (int i = 0; i < 9; i++)
        #pragma unroll
        for (int j = 0; j < 9; j++)
            atomicAdd(&Sg[(ti * 9 + i) * SDIM + (tj * 9 + j)], acc[i * 9 + j]);
}

// ---------------- kernel 4: per (b,h) attention head from S (smem-resident, reg-tiled) ----------------
// dyn smem layout (floats):
//   S_sm  [144 x 145]  @0        (20880)
//   Wk_sm [128 x 145]  @20880    (18560)   (overlaid by M[32x128] after softmax)
//   Wq_sm [16 x 144]   @39440    (2304)
//   T_sm  [16 x 144]   @41744    (2304)
//   G     [16 x 128]   @44048    (2048)    total 46096 floats = 184384 B
__global__ void __launch_bounds__(512) k_attn(const float* __restrict__ w_out) {
    extern __shared__ float pool[];
    float* S_sm  = pool;
    float* Wk_sm = pool + 20880;
    float* Wq_sm = pool + 39440;
    float* T_sm  = pool + 41744;
    float* G     = pool + 44048;
    float* M     = Wk_sm;          // overlay after Wk is consumed
    __shared__ float nq[16], nk[128], red[512];

    int bh = blockIdx.x;
    int b = bh >> 2, h = bh & 3;
    int t = threadIdx.x;
    const float* Sg = g_S[bh];

    for (int idx = t; idx < SDIM * SDIM; idx += 512) {
        int r = idx / SDIM, c = idx - r * SDIM;
        S_sm[r * 145 + c] = Sg[idx];
    }
    for (int idx = t; idx < 128 * SDIM; idx += 512) {
        int r = idx / SDIM, c = idx - r * SDIM;
        Wk_sm[r * 145 + c] = (&g_Wk[h][0][0])[idx];
    }
    for (int idx = t; idx < 16 * SDIM; idx += 512)
        Wq_sm[idx] = (&g_Wq[h][0][0])[idx];
    __syncthreads();

    // T = Wq * S  (tiled: 4 output cols per work item; 576 items)
    for (int g = t; g < 576; g += 512) {
        int q = g / 36, i0 = (g - q * 36) * 4;
        float a0 = 0.0f, a1 = 0.0f, a2 = 0.0f, a3 = 0.0f;
        const float* wqr = Wq_sm + q * SDIM;
        #pragma unroll 4
        for (int j = 0; j < SDIM; j++) {
            float wv = wqr[j];
            const float* sr = S_sm + j * 145 + i0;
            a0 = fmaf(wv, sr[0], a0);
            a1 = fmaf(wv, sr[1], a1);
            a2 = fmaf(wv, sr[2], a2);
            a3 = fmaf(wv, sr[3], a3);
        }
        float* tr = T_sm + q * SDIM + i0;
        tr[0] = a0; tr[1] = a1; tr[2] = a2; tr[3] = a3;
    }
    __syncthreads();

    // ||Q_q||^2 = T_q . Wq_q
    if (t < 16) {
        float a = 0.0f;
        for (int i = 0; i < SDIM; i++)
            a = fmaf(T_sm[t * SDIM + i], Wq_sm[t * SDIM + i], a);
        nq[t] = fmaxf(sqrtf(fmaxf(a, 0.0f)), 1e-12f);
    }

    // G[q][k] = T_q . Wk_k   (tiled: q = t>>5, 4 k per thread)
    {
        int q = t >> 5, k0 = (t & 31) * 4;
        float a0 = 0.0f, a1 = 0.0f, a2 = 0.0f, a3 = 0.0f;
        const float* tq = T_sm + q * SDIM;
        const float* w0 = Wk_sm + (k0 + 0) * 145;
        const float* w1 = Wk_sm + (k0 + 1) * 145;
        const float* w2 = Wk_sm + (k0 + 2) * 145;
        const float* w3 = Wk_sm + (k0 + 3) * 145;
        #pragma unroll 4
        for (int i = 0; i < SDIM; i++) {
            float tv = tq[i];
            a0 = fmaf(tv, w0[i], a0);
            a1 = fmaf(tv, w1[i], a1);
            a2 = fmaf(tv, w2[i], a2);
            a3 = fmaf(tv, w3[i], a3);
        }
        G[q * 128 + k0 + 0] = a0;
        G[q * 128 + k0 + 1] = a1;
        G[q * 128 + k0 + 2] = a2;
        G[q * 128 + k0 + 3] = a3;
    }

    // ||K_k||^2 = Wk_k S Wk_k^T   (128 k x 4 row-groups of 36, i tiled by 4)
    // S loads broadcast across the warp (i constant within warp), Wk conflict-free.
    {
        int k = t & 127, g = t >> 7;
        const float* wk_r = Wk_sm + k * 145;
        float a = 0.0f;
        #pragma unroll 1
        for (int qd = 0; qd < 9; qd++) {
            int i0 = g * 36 + qd * 4;
            float r0 = 0.0f, r1 = 0.0f, r2 = 0.0f, r3 = 0.0f;
            const float* s0 = S_sm + (i0 + 0) * 145;
            const float* s1 = S_sm + (i0 + 1) * 145;
            const float* s2 = S_sm + (i0 + 2) * 145;
            const float* s3 = S_sm + (i0 + 3) * 145;
            #pragma unroll 4
            for (int j = 0; j < SDIM; j++) {
                float wv = wk_r[j];
                r0 = fmaf(s0[j], wv, r0);
                r1 = fmaf(s1[j], wv, r1);
                r2 = fmaf(s2[j], wv, r2);
                r3 = fmaf(s3[j], wv, r3);
            }
            a = fmaf(wk_r[i0 + 0], r0, a);
            a = fmaf(wk_r[i0 + 1], r1, a);
            a = fmaf(wk_r[i0 + 2], r2, a);
            a = fmaf(wk_r[i0 + 3], r3, a);
        }
        red[t] = a;
    }
    __syncthreads();
    if (t < 128) {
        float sum = red[t] + red[t + 128] + red[t + 256] + red[t + 384];
        nk[t] = fmaxf(sqrtf(fmaxf(sum, 0.0f)), 1e-12f);
    }
    __syncthreads();

    // score = G / (|Q||K| sqrt(N)); sqrt(36864) = 192
    for (int idx = t; idx < 2048; idx += 512) {
        int q = idx >> 7, k = idx & 127;
        G[idx] = G[idx] / (nq[q] * nk[k] * 192.0f);
    }
    __syncthreads();

    // instance norm over 16x128
    float lsum = 0.0f;
    for (int idx = t; idx < 2048; idx += 512) lsum += G[idx];
    red[t] = lsum; __syncthreads();
    for (int st = 256; st > 0; st >>= 1) { if (t < st) red[t] += red[t + st]; __syncthreads(); }
    float mean = red[0] * (1.0f / 2048.0f);
    __syncthreads();
    float lss = 0.0f;
    for (int idx = t; idx < 2048; idx += 512) { float d = G[idx] - mean; lss = fmaf(d, d, lss); }
    red[t] = lss; __syncthreads();
    for (int st = 256; st > 0; st >>= 1) { if (t < st) red[t] += red[t + st]; __syncthreads(); }
    float var = red[0] * (1.0f / 2048.0f);
    float iscale = rsqrtf(var + 1e-5f);
    __syncthreads();
    for (int idx = t; idx < 2048; idx += 512)
        G[idx] = (G[idx] - mean) * iscale;
    __syncthreads();

    // softmax over k per row (16 warps x 1 row)
    int wid = t >> 5, lane = t & 31;
    {
        int q = wid;
        float m = -1e30f;
        for (int k = lane; k < 128; k += 32) m = fmaxf(m, G[q * 128 + k]);
        #pragma unroll
        for (int o = 16; o > 0; o >>= 1) m = fmaxf(m, __shfl_xor_sync(0xffffffffu, m, o));
        float ssum = 0.0f;
        for (int k = lane; k < 128; k += 32) {
            float e = expf(G[q * 128 + k] - m);
            G[q * 128 + k] = e;
            ssum += e;
        }
        #pragma unroll
        for (int o = 16; o > 0; o >>= 1) ssum += __shfl_xor_sync(0xffffffffu, ssum, o);
        float inv = 1.0f / ssum;
        for (int k = lane; k < 128; k += 32) G[q * 128 + k] *= inv;
    }
    __syncthreads();

    // M[o][k] = sum_q w_out[o, h*16+q] attn[q][k]   (M overlays Wk_sm)
    float mv[8];
    {
        #pragma unroll
        for (int r = 0; r < 8; r++) {
            int idx = t + r * 512;
            int o = idx >> 7, k = idx & 127;
            float a = 0.0f;
            #pragma unroll
            for (int q = 0; q < 16; q++)
                a = fmaf(w_out[o * 64 + h * 16 + q], G[q * 128 + k], a);
            mv[r] = a;
        }
    }
    __syncthreads();   // all reads of Wk_sm done before overlay write
    #pragma unroll
    for (int r = 0; r < 8; r++) M[t + r * 512] = mv[r];
    __syncthreads();

    // Weff2[o][i] = sum_k M[o][k] Wv[k][i]  (tiled: 4 i per work item; 1152 items)
    for (int g = t; g < OCH * 36; g += 512) {
        int o = g / 36, i0 = (g - o * 36) * 4;
        float a0 = 0.0f, a1 = 0.0f, a2 = 0.0f, a3 = 0.0f;
        const float* mo = M + o * 128;
        #pragma unroll 4
        for (int k = 0; k < 128; k++) {
            float mvv = mo[k];
            const float* wvr = &g_Wv[h][k][i0];
            a0 = fmaf(mvv, wvr[0], a0);
            a1 = fmaf(mvv, wvr[1], a1);
            a2 = fmaf(mvv, wvr[2], a2);
            a3 = fmaf(mvv, wvr[3], a3);
        }
        float* w2r = &g_W2[b][h][o][i0];
        w2r[0] = a0; w2r[1] = a1; w2r[2] = a2; w2r[3] = a3;
    }
}

// ---------------- kernel 5: fused output conv (4 dilated 3x3 convs, f32x2) + BN stats ----------------
// grid (48 x-groups of 4 rows, Bb), 256 threads = 8 warps (o-groups of 4) x 32 lanes (y-groups of 6)
__global__ void __launch_bounds__(256) k_out(const float* __restrict__ cen, float* __restrict__ out) {
    extern __shared__ float dsm[];
    float* insm = dsm;                 // Cc*3*W2 = 10272 floats
    float* W2sm = dsm + Cc * 3 * W2;   // OCH*SDIM = 4608 floats

    int xg = blockIdx.x, b = blockIdx.y;
    int t = threadIdx.x;
    int ty = t & 31, to = t >> 5;
    const float* cb = cen + (size_t)b * Cc * NPIX;

    for (int xr = 0; xr < 4; xr++) {
        int x = xg * 4 + xr;
        ull acc2[4][3];
        #pragma unroll
        for (int oo = 0; oo < 4; oo++)
            #pragma unroll
            for (int j = 0; j < 3; j++) acc2[oo][j] = 0ull;

        for (int h = 0; h < Hh; h++) {
            int s = c_shift[h];
            int plen = HT + 2 * s;
            __syncthreads();
            for (int idx = t; idx < Cc * 3 * plen; idx += 256) {
                int c = idx / (3 * plen);
                int rem = idx - c * 3 * plen;
                int r = rem / plen;
                int p = rem - r * plen;
                int xx = x + (r - 1) * s;
                int y = p - s;
                float v = 0.0f;
                if (xx >= 0 && xx < WD && y >= 0 && y < HT)
                    v = cb[((size_t)c * WD + xx) * HT + y];
                insm[c * (3 * W2) + r * W2 + p] = v;
            }
            for (int idx = t; idx < OCH * SDIM; idx += 256)
                W2sm[idx] = (&g_W2[b][h][0][0])[idx];
            __syncthreads();

            int ybase = ty * 6;
            #pragma unroll 1
            for (int c = 0; c < Cc; c++) {
                const float* pc = insm + c * (3 * W2);
                #pragma unroll
                for (int d = 0; d < 9; d++) {
                    const float* px = pc + (d / 3) * W2 + (d % 3) * s + ybase;
                    float w0 = W2sm[(to * 4 + 0) * SDIM + c * 9 + d];
                    float w1 = W2sm[(to * 4 + 1) * SDIM + c * 9 + d];
                    float w2 = W2sm[(to * 4 + 2) * SDIM + c * 9 + d];
                    float w3 = W2sm[(to * 4 + 3) * SDIM + c * 9 + d];
                    ull w0p = pk2(w0, w0), w1p = pk2(w1, w1);
                    ull w2p = pk2(w2, w2), w3p = pk2(w3, w3);
                    #pragma unroll
                    for (int j = 0; j < 3; j++) {
                        ull xv = pk2(px[2 * j], px[2 * j + 1]);
                        acc2[0][j] = ffma2(w0p, xv, acc2[0][j]);
                        acc2[1][j] = ffma2(w1p, xv, acc2[1][j]);
                        acc2[2][j] = ffma2(w2p, xv, acc2[2][j]);
                        acc2[3][j] = ffma2(w3p, xv, acc2[3][j]);
                    }
                }
            }
        }

        // write raw y + accumulate BN stats
        #pragma unroll
        for (int oo = 0; oo < 4; oo++) {
            int o = to * 4 + oo;
            float s1 = 0.0f, s2 = 0.0f;
            float* op = out + (((size_t)b * OCH + o) * WD + x) * HT + ty * 6;
            #pragma unroll
            for (int j = 0; j < 3; j++) {
                float lo, hi;
                upk2(acc2[oo][j], lo, hi);
                op[2 * j]     = lo;
                op[2 * j + 1] = hi;
                s1 += lo + hi;
                s2 = fmaf(lo, lo, s2);
                s2 = fmaf(hi, hi, s2);
            }
            #pragma unroll
            for (int off2 = 16; off2 > 0; off2 >>= 1) {
                s1 += __shfl_xor_sync(0xffffffffu, s1, off2);
                s2 += __shfl_xor_sync(0xffffffffu, s2, off2);
            }
            if (ty == 0) {
                atomicAdd(&g_bnsum[o], s1);
                atomicAdd(&g_bnsq[o], s2);
            }
        }
    }
}

// ---------------- kernel 6: batchnorm (train stats) + ReLU, in place ----------------
__global__ void k_bn(float* __restrict__ out, const float* __restrict__ gamma,
                     const float* __restrict__ beta) {
    __shared__ float ssc[OCH], sbi[OCH];
    if (threadIdx.x < OCH) {
        int o = threadIdx.x;
        float invN = 1.0f / ((float)Bb * NPIX);
        float m = g_bnsum[o] * invN;
        float v = g_bnsq[o] * invN - m * m;
        float sc = gamma[o] * rsqrtf(v + 1e-5f);
        ssc[o] = sc;
        sbi[o] = beta[o] - m * sc;
    }
    __syncthreads();
    size_t total = (size_t)Bb * OCH * NPIX;
    for (size_t i = (size_t)blockIdx.x * blockDim.x + threadIdx.x; i < total;
         i += (size_t)gridDim.x * blockDim.x) {
        int o = (int)((i / NPIX) & 31);
        float v = fmaf(out[i], ssc[o], sbi[o]);
        out[i] = fmaxf(v, 0.0f);
    }
}

// ---------------- launch ----------------
extern "C" void kernel_launch(void* const* d_in, const int* in_sizes, int n_in,
                              void* d_out, int out_size) {
    (void)in_sizes; (void)n_in; (void)out_size;
    const float* cen   = (const float*)d_in[0];
    const float* wq    = (const float*)d_in[1];
    const float* wk    = (const float*)d_in[2];
    const float* wv    = (const float*)d_in[3];
    const float* sum_w = (const float*)d_in[4];
    const float* w_out = (const float*)d_in[5];
    const float* gamma = (const float*)d_in[6];
    const float* beta  = (const float*)d_in[7];
    float* out = (float*)d_out;

    int dynsmem_out  = (Cc * 3 * W2 + OCH * SDIM) * (int)sizeof(float);
    int dynsmem_attn = 46096 * (int)sizeof(float);
    cudaFuncSetAttribute(k_out,  cudaFuncAttributeMaxDynamicSharedMemorySize, dynsmem_out);
    cudaFuncSetAttribute(k_attn, cudaFuncAttributeMaxDynamicSharedMemorySize, dynsmem_attn);

    k_prep<<<4, 256>>>(wq, wk, wv, sum_w);
    k_zero<<<1024, 256>>>();
    k_S<<<dim3(24, 4, 8), 256>>>(cen);
    k_attn<<<32, 512, dynsmem_attn>>>(w_out);
    k_out<<<dim3(48, 8), 256, dynsmem_out>>>(cen, out);
    k_bn<<<2048, 256>>>(out, gamma, beta);
}

// round 8
// speedup vs baseline: 1.6162x; 1.1516x over previous
#include <cuda_runtime.h>
#include <math.h>

#define Bb 8
#define Cc 16
#define WD 192
#define HT 192
#define NPIX (WD*HT)
#define Hh 4
#define HID 16
#define OCH 32
#define W2 214
#define SDIM 144

typedef unsigned long long ull;

// ---------------- packed f32x2 helpers (k_out) ----------------
__device__ __forceinline__ ull pk2(float lo, float hi) {
    ull u;
    asm("mov.b64 %0, {%1, %2};" : "=l"(u) : "f"(lo), "f"(hi));
    return u;
}
__device__ __forceinline__ void upk2(ull u, float& lo, float& hi) {
    asm("mov.b64 {%0, %1}, %2;" : "=f"(lo), "=f"(hi) : "l"(u));
}
__device__ __forceinline__ ull ffma2(ull a, ull b, ull c) {
    ull d;
    asm("fma.rn.f32x2 %0, %1, %2, %3;" : "=l"(d) : "l"(a), "l"(b), "l"(c));
    return d;
}

// ---------------- device scratch ----------------
__device__ float g_Wq[Hh][HID][SDIM];
__device__ float g_Wk[Hh][128][SDIM];
__device__ float g_Wv[Hh][128][SDIM];
__device__ float g_W2[Bb][Hh][OCH][SDIM];
__device__ float g_bnsum[OCH];
__device__ float g_bnsq[OCH];

// correlation tables: [bh][pair=c1*16+c2][lag dd=ix*5+iy], ix=dx/s+2, iy=dy/s+2
__device__ float g_F [32][256][25];
__device__ float g_SxS[2][32][256][25];   // [0]=low-x strip (qx in [0,s)), [1]=high-x
__device__ float g_SyS[2][32][256][25];   // [0]=low-y, [1]=high-y
__device__ float g_Cn [4][32][256][25];   // [cx*2+cy], cx/cy: 0=low,1=high

__constant__ int c_shift[4] = {1, 2, 4, 8};
__constant__ int c_off[8]   = {0, 1, 2, 5, 8, 7, 6, 3};

// ---------------- kernel 1: fold blend kernels into effective conv weights ----------------
__global__ void k_prep(const float* __restrict__ wq, const float* __restrict__ wk,
                       const float* __restrict__ wv, const float* __restrict__ sum_w) {
    int h = blockIdx.x;
    int t = threadIdx.x;
    __shared__ float wcen[Cc][9];
    __shared__ float wsur[Cc][8][9];

    if (t < Cc * 9) {
        int c = t / 9, d = t % 9;
        float sw = sum_w[h * Cc + c];
        float su_f = (d == 4) ? 0.125f : (7.0f / 64.0f);
        float ce   = (d == 4) ? 1.0f : 0.0f;
        wcen[c][d] = su_f * (1.0f - sw) + ce * sw;
    }
    for (int idx = t; idx < Cc * 8 * 9; idx += 256) {
        int c = idx / 72;
        int k = (idx / 9) % 8;
        int d = idx % 9;
        float sw = sum_w[h * Cc + c];
        float delta = ((d == 4) ? 1.0f : 0.0f) + ((d == c_off[k]) ? -1.0f : 0.0f);
        float ce    = (d == 4) ? 1.0f : 0.0f;
        float k2w   = (delta - ce) * 1.125f + 0.125f;
        wsur[c][k][d] = delta * (1.0f - sw) + k2w * sw;
    }
    __syncthreads();

    for (int idx = t; idx < HID * SDIM; idx += 256) {
        int q = idx / SDIM, c = (idx % SDIM) / 9, d = idx % 9;
        g_Wq[h][q][c * 9 + d] = wq[(h * HID + q) * Cc + c] * wcen[c][d];
    }
    for (int idx = t; idx < 128 * SDIM; idx += 256) {
        int o = idx / SDIM, c = (idx % SDIM) / 9, d = idx % 9;
        float ak = 0.0f, av = 0.0f;
        #pragma unroll
        for (int k = 0; k < 8; k++) {
            float ws = wsur[c][k][d];
            ak = fmaf(wk[(h * 128 + o) * 128 + k * Cc + c], ws, ak);
            av = fmaf(wv[(h * 128 + o) * 128 + k * Cc + c], ws, av);
        }
        g_Wk[h][o][c * 9 + d] = ak;
        g_Wv[h][o][c * 9 + d] = av;
    }
}

// ---------------- kernel 2: zero accumulators ----------------
__global__ void k_zero() {
    const long per = 32L * 256 * 25;
    long stride = (long)gridDim.x * 256;
    long i0 = (long)blockIdx.x * 256 + threadIdx.x;
    for (long i = i0; i < per; i += stride) (&g_F[0][0][0])[i] = 0.0f;
    for (long i = i0; i < 2 * per; i += stride) (&g_SxS[0][0][0][0])[i] = 0.0f;
    for (long i = i0; i < 2 * per; i += stride) (&g_SyS[0][0][0][0])[i] = 0.0f;
    if (blockIdx.x == 0 && threadIdx.x < OCH) {
        g_bnsum[threadIdx.x] = 0.0f;
        g_bnsq[threadIdx.x]  = 0.0f;
    }
}

// ---------------- kernel 3a: full-domain correlations F(dd) for dd=12..24 ----------------
// grid (8 x-chunks of 24 rows, Hh, Bb), 256 threads = (c1 = t&15, c2 = t>>4).
// F[dd] = sum_{q in [0,192)^2} x(c1,q) * xpad(c2, q+delta),  delta = ((ix-2)s,(iy-2)s)
// smem: per channel 3 rows (qx, qx+s, qx+2s), padded y by 16 each side (width 224),
// channel stride 673 (=3*224+1) for conflict-free a-loads.
__global__ void __launch_bounds__(256) k_corrF(const float* __restrict__ cen) {
    __shared__ float st[16 * 673];
    int xc = blockIdx.x, h = blockIdx.y, b = blockIdx.z;
    int s = c_shift[h];
    int bh = b * Hh + h;
    int t = threadIdx.x;
    int c1 = t & 15, c2 = t >> 4;
    const float* cb = cen + (size_t)b * Cc * NPIX;

    float acc[13];
    #pragma unroll
    for (int i = 0; i < 13; i++) acc[i] = 0.0f;

    for (int qx = xc * 24; qx < xc * 24 + 24; qx++) {
        __syncthreads();
        for (int idx = t; idx < 16 * 673; idx += 256) {
            int c = idx / 673;
            int rm = idx - c * 673;
            float v = 0.0f;
            if (rm < 672) {
                int k = rm / 224, j = rm - k * 224;
                int r = qx + k * s;
                int y = j - 16;
                if (r < WD && y >= 0 && y < HT)
                    v = cb[((size_t)c * WD + r) * HT + y];
            }
            st[idx] = v;
        }
        __syncthreads();

        const float* ar = st + c1 * 673 + 16;
        const float* b0 = st + c2 * 673 + 16;
        const float* b1 = b0 + 224;
        const float* b2 = b1 + 224;
        int s2 = 2 * s;
        #pragma unroll 4
        for (int qy = 0; qy < HT; qy++) {
            float a = ar[qy];
            acc[0] = fmaf(a, b0[qy],      acc[0]);   // (0,0)    dd=12
            acc[1] = fmaf(a, b0[qy + s],  acc[1]);   // (0,+s)   dd=13
            acc[2] = fmaf(a, b0[qy + s2], acc[2]);   // (0,+2s)  dd=14
            #pragma unroll
            for (int iy = 0; iy < 5; iy++)           // (+s, dy) dd=15..19
                acc[3 + iy] = fmaf(a, b1[qy + (iy - 2) * s], acc[3 + iy]);
            #pragma unroll
            for (int iy = 0; iy < 5; iy++)           // (+2s,dy) dd=20..24
                acc[8 + iy] = fmaf(a, b2[qy + (iy - 2) * s], acc[8 + iy]);
        }
    }
    float* dst = &g_F[bh][c1 * 16 + c2][12];
    #pragma unroll
    for (int i = 0; i < 13; i++) atomicAdd(dst + i, acc[i]);
}

// ---------------- kernel 3b: x-border strips, all 25 lags (dynamic smem: 71744 B) ----------------
// grid (8 = side(2) x ychunk(4), Hh, Bb); strip qx in [x0, x0+s), qy in chunk of 48.
__global__ void __launch_bounds__(256) k_stripx(const float* __restrict__ cen) {
    extern __shared__ float st[];     // 16 * 1121 floats: 5 rows x 224 per channel, stride 1121
    int side = blockIdx.x & 1, chunk = blockIdx.x >> 1;
    int h = blockIdx.y, b = blockIdx.z;
    int s = c_shift[h];
    int bh = b * Hh + h;
    int t = threadIdx.x;
    int c1 = t & 15, c2 = t >> 4;
    const float* cb = cen + (size_t)b * Cc * NPIX;
    int x0 = side ? (WD - s) : 0;

    float acc[25];
    #pragma unroll
    for (int i = 0; i < 25; i++) acc[i] = 0.0f;

    for (int qq = 0; qq < s; qq++) {
        int qx = x0 + qq;
        __syncthreads();
        for (int idx = t; idx < 16 * 1121; idx += 256) {
            int c = idx / 1121;
            int rm = idx - c * 1121;
            float v = 0.0f;
            if (rm < 1120) {
                int k = rm / 224, j = rm - k * 224;
                int r = qx + (k - 2) * s;
                int y = j - 16;
                if (r >= 0 && r < WD && y >= 0 && y < HT)
                    v = cb[((size_t)c * WD + r) * HT + y];
            }
            st[idx] = v;
        }
        __syncthreads();

        const float* ar = st + c1 * 1121 + 2 * 224 + 16;
        const float* base2 = st + c2 * 1121;
        for (int qy = chunk * 48; qy < chunk * 48 + 48; qy++) {
            float a = ar[qy];
            #pragma unroll
            for (int ix = 0; ix < 5; ix++) {
                const float* br = base2 + ix * 224 + 16 + qy;
                #pragma unroll
                for (int iy = 0; iy < 5; iy++)
                    acc[ix * 5 + iy] = fmaf(a, br[(iy - 2) * s], acc[ix * 5 + iy]);
            }
        }
    }
    float* dst = &g_SxS[side][bh][c1 * 16 + c2][0];
    #pragma unroll
    for (int i = 0; i < 25; i++) atomicAdd(dst + i, acc[i]);
}

// ---------------- kernel 3c: y-border strips, all 25 lags ----------------
// grid (8 = side(2) x xchunk(4), Hh, Bb); strip qy in [y0, y0+s), qx in chunk of 48.
__global__ void __launch_bounds__(256) k_stripy(const float* __restrict__ cen) {
    __shared__ float yw[16 * 201];    // 5 rows x 40-wide y-window per channel, stride 201
    int side = blockIdx.x & 1, chunk = blockIdx.x >> 1;
    int h = blockIdx.y, b = blockIdx.z;
    int s = c_shift[h];
    int bh = b * Hh + h;
    int t = threadIdx.x;
    int c1 = t & 15, c2 = t >> 4;
    const float* cb = cen + (size_t)b * Cc * NPIX;
    int y0 = side ? (HT - s) : 0;
    int jbase = y0 - 2 * s;

    float acc[25];
    #pragma unroll
    for (int i = 0; i < 25; i++) acc[i] = 0.0f;

    for (int qx = chunk * 48; qx < chunk * 48 + 48; qx++) {
        __syncthreads();
        for (int idx = t; idx < 16 * 201; idx += 256) {
            int c = idx / 201;
            int rm = idx - c * 201;
            float v = 0.0f;
            if (rm < 200) {
                int k = rm / 40, j = rm - k * 40;
                int r = qx + (k - 2) * s;
                int y = jbase + j;
                if (r >= 0 && r < WD && y >= 0 && y < HT)
                    v = cb[((size_t)c * WD + r) * HT + y];
            }
            yw[idx] = v;
        }
        __syncthreads();

        const float* ar = yw + c1 * 201 + 2 * 40 + 2 * s;   // x1 row (k=2), j=2s+jj
        const float* base2 = yw + c2 * 201;
        for (int jj = 0; jj < s; jj++) {
            float a = ar[jj];
            #pragma unroll
            for (int ix = 0; ix < 5; ix++) {
                const float* br = base2 + ix * 40 + 2 * s + jj;
                #pragma unroll
                for (int iy = 0; iy < 5; iy++)
                    acc[ix * 5 + iy] = fmaf(a, br[(iy - 2) * s], acc[ix * 5 + iy]);
            }
        }
    }
    float* dst = &g_SyS[side][bh][c1 * 16 + c2][0];
    #pragma unroll
    for (int i = 0; i < 25; i++) atomicAdd(dst + i, acc[i]);
}

// ---------------- kernel 3d: s x s corner patches, all 25 lags ----------------
// grid (4 corners, Hh, Bb); direct global loads (tiny), direct store.
__global__ void __launch_bounds__(256) k_corner(const float* __restrict__ cen) {
    int corner = blockIdx.x;
    int cx = corner >> 1, cy = corner & 1;
    int h = blockIdx.y, b = blockIdx.z;
    int s = c_shift[h];
    int bh = b * Hh + h;
    int t = threadIdx.x;
    int c1 = t & 15, c2 = t >> 4;
    const float* cb = cen + (size_t)b * Cc * NPIX;
    int x0 = cx ? (WD - s) : 0;
    int y0 = cy ? (HT - s) : 0;

    float acc[25];
    #pragma unroll
    for (int i = 0; i < 25; i++) acc[i] = 0.0f;

    for (int i = 0; i < s; i++) {
        for (int j = 0; j < s; j++) {
            int qx = x0 + i, qy = y0 + j;
            float a = cb[((size_t)c1 * WD + qx) * HT + qy];
            #pragma unroll
            for (int ix = 0; ix < 5; ix++) {
                int bx = qx + (ix - 2) * s;
                #pragma unroll
                for (int iy = 0; iy < 5; iy++) {
                    int by = qy + (iy - 2) * s;
                    float bv = (bx >= 0 && bx < WD && by >= 0 && by < HT)
                               ? cb[((size_t)c2 * WD + bx) * HT + by] : 0.0f;
                    acc[ix * 5 + iy] = fmaf(a, bv, acc[ix * 5 + iy]);
                }
            }
        }
    }
    float* dst = &g_Cn[corner][bh][c1 * 16 + c2][0];
    #pragma unroll
    for (int i = 0; i < 25; i++) dst[i] = acc[i];
}

// ---------------- kernel 3e: mirror fill F for dd<12 via F_{c1,c2}(d)=F_{c2,c1}(24-d) ----------------
__global__ void k_mirrorF() {
    int bh = blockIdx.x;
    int p = threadIdx.x;           // 256 ordered pairs
    int cA = p >> 4, cB = p & 15;  // p = cA*16+cB
    int ps = cB * 16 + cA;
    #pragma unroll
    for (int d = 0; d < 12; d++)
        g_F[bh][p][d] = g_F[bh][ps][24 - d];
}

// ---------------- kernel 4: per (b,h) attention head (assembles S from corr tables) ----------------
__global__ void __launch_bounds__(512) k_attn(const float* __restrict__ w_out) {
    extern __shared__ float pool[];
    float* S_sm  = pool;
    float* Wk_sm = pool + 20880;
    float* Wq_sm = pool + 39440;
    float* T_sm  = pool + 41744;
    float* G     = pool + 44048;
    float* M     = Wk_sm;
    __shared__ float nq[16], nk[128], red[512];

    int bh = blockIdx.x;
    int b = bh >> 2, h = bh & 3;
    int t = threadIdx.x;

    // assemble S[(c1,d1)][(c2,d2)] = F - strips + corner
    for (int idx = t; idx < SDIM * SDIM; idx += 512) {
        int r = idx / SDIM, c = idx - r * SDIM;
        int c1 = r / 9, d1 = r - c1 * 9;
        int c2 = c / 9, d2 = c - c2 * 9;
        int o1x = d1 / 3 - 1, o1y = d1 % 3 - 1;
        int o2x = d2 / 3 - 1, o2y = d2 % 3 - 1;
        int dd = (o2x - o1x + 2) * 5 + (o2y - o1y + 2);
        int p = c1 * 16 + c2;
        float v = g_F[bh][p][dd];
        if (o1x > 0)      v -= g_SxS[0][bh][p][dd];
        else if (o1x < 0) v -= g_SxS[1][bh][p][dd];
        if (o1y > 0)      v -= g_SyS[0][bh][p][dd];
        else if (o1y < 0) v -= g_SyS[1][bh][p][dd];
        if (o1x != 0 && o1y != 0) {
            int ci = ((o1x > 0) ? 0 : 2) + ((o1y > 0) ? 0 : 1);
            v += g_Cn[ci][bh][p][dd];
        }
        S_sm[r * 145 + c] = v;
    }
    for (int idx = t; idx < 128 * SDIM; idx += 512) {
        int r = idx / SDIM, c = idx - r * SDIM;
        Wk_sm[r * 145 + c] = (&g_Wk[h][0][0])[idx];
    }
    for (int idx = t; idx < 16 * SDIM; idx += 512)
        Wq_sm[idx] = (&g_Wq[h][0][0])[idx];
    __syncthreads();

    // T = Wq * S
    for (int g = t; g < 576; g += 512) {
        int q = g / 36, i0 = (g - q * 36) * 4;
        float a0 = 0.0f, a1 = 0.0f, a2 = 0.0f, a3 = 0.0f;
        const float* wqr = Wq_sm + q * SDIM;
        #pragma unroll 4
        for (int j = 0; j < SDIM; j++) {
            float wv = wqr[j];
            const float* sr = S_sm + j * 145 + i0;
            a0 = fmaf(wv, sr[0], a0);
            a1 = fmaf(wv, sr[1], a1);
            a2 = fmaf(wv, sr[2], a2);
            a3 = fmaf(wv, sr[3], a3);
        }
        float* tr = T_sm + q * SDIM + i0;
        tr[0] = a0; tr[1] = a1; tr[2] = a2; tr[3] = a3;
    }
    __syncthreads();

    if (t < 16) {
        float a = 0.0f;
        for (int i = 0; i < SDIM; i++)
            a = fmaf(T_sm[t * SDIM + i], Wq_sm[t * SDIM + i], a);
        nq[t] = fmaxf(sqrtf(fmaxf(a, 0.0f)), 1e-12f);
    }

    {
        int q = t >> 5, k0 = (t & 31) * 4;
        float a0 = 0.0f, a1 = 0.0f, a2 = 0.0f, a3 = 0.0f;
        const float* tq = T_sm + q * SDIM;
        const float* w0 = Wk_sm + (k0 + 0) * 145;
        const float* w1 = Wk_sm + (k0 + 1) * 145;
        const float* w2 = Wk_sm + (k0 + 2) * 145;
        const float* w3 = Wk_sm + (k0 + 3) * 145;
        #pragma unroll 4
        for (int i = 0; i < SDIM; i++) {
            float tv = tq[i];
            a0 = fmaf(tv, w0[i], a0);
            a1 = fmaf(tv, w1[i], a1);
            a2 = fmaf(tv, w2[i], a2);
            a3 = fmaf(tv, w3[i], a3);
        }
        G[q * 128 + k0 + 0] = a0;
        G[q * 128 + k0 + 1] = a1;
        G[q * 128 + k0 + 2] = a2;
        G[q * 128 + k0 + 3] = a3;
    }

    {
        int k = t & 127, g = t >> 7;
        const float* wk_r = Wk_sm + k * 145;
        float a = 0.0f;
        #pragma unroll 1
        for (int qd = 0; qd < 9; qd++) {
            int i0 = g * 36 + qd * 4;
            float r0 = 0.0f, r1 = 0.0f, r2 = 0.0f, r3 = 0.0f;
            const float* s0 = S_sm + (i0 + 0) * 145;
            const float* s1 = S_sm + (i0 + 1) * 145;
            const float* s2 = S_sm + (i0 + 2) * 145;
            const float* s3 = S_sm + (i0 + 3) * 145;
            #pragma unroll 4
            for (int j = 0; j < SDIM; j++) {
                float wv = wk_r[j];
                r0 = fmaf(s0[j], wv, r0);
                r1 = fmaf(s1[j], wv, r1);
                r2 = fmaf(s2[j], wv, r2);
                r3 = fmaf(s3[j], wv, r3);
            }
            a = fmaf(wk_r[i0 + 0], r0, a);
            a = fmaf(wk_r[i0 + 1], r1, a);
            a = fmaf(wk_r[i0 + 2], r2, a);
            a = fmaf(wk_r[i0 + 3], r3, a);
        }
        red[t] = a;
    }
    __syncthreads();
    if (t < 128) {
        float sum = red[t] + red[t + 128] + red[t + 256] + red[t + 384];
        nk[t] = fmaxf(sqrtf(fmaxf(sum, 0.0f)), 1e-12f);
    }
    __syncthreads();

    for (int idx = t; idx < 2048; idx += 512) {
        int q = idx >> 7, k = idx & 127;
        G[idx] = G[idx] / (nq[q] * nk[k] * 192.0f);
    }
    __syncthreads();

    float lsum = 0.0f;
    for (int idx = t; idx < 2048; idx += 512) lsum += G[idx];
    red[t] = lsum; __syncthreads();
    for (int st = 256; st > 0; st >>= 1) { if (t < st) red[t] += red[t + st]; __syncthreads(); }
    float mean = red[0] * (1.0f / 2048.0f);
    __syncthreads();
    float lss = 0.0f;
    for (int idx = t; idx < 2048; idx += 512) { float d = G[idx] - mean; lss = fmaf(d, d, lss); }
    red[t] = lss; __syncthreads();
    for (int st = 256; st > 0; st >>= 1) { if (t < st) red[t] += red[t + st]; __syncthreads(); }
    float var = red[0] * (1.0f / 2048.0f);
    float iscale = rsqrtf(var + 1e-5f);
    __syncthreads();
    for (int idx = t; idx < 2048; idx += 512)
        G[idx] = (G[idx] - mean) * iscale;
    __syncthreads();

    int wid = t >> 5, lane = t & 31;
    {
        int q = wid;
        float m = -1e30f;
        for (int k = lane; k < 128; k += 32) m = fmaxf(m, G[q * 128 + k]);
        #pragma unroll
        for (int o = 16; o > 0; o >>= 1) m = fmaxf(m, __shfl_xor_sync(0xffffffffu, m, o));
        float ssum = 0.0f;
        for (int k = lane; k < 128; k += 32) {
            float e = expf(G[q * 128 + k] - m);
            G[q * 128 + k] = e;
            ssum += e;
        }
        #pragma unroll
        for (int o = 16; o > 0; o >>= 1) ssum += __shfl_xor_sync(0xffffffffu, ssum, o);
        float inv = 1.0f / ssum;
        for (int k = lane; k < 128; k += 32) G[q * 128 + k] *= inv;
    }
    __syncthreads();

    float mv[8];
    {
        #pragma unroll
        for (int r = 0; r < 8; r++) {
            int idx = t + r * 512;
            int o = idx >> 7, k = idx & 127;
            float a = 0.0f;
            #pragma unroll
            for (int q = 0; q < 16; q++)
                a = fmaf(w_out[o * 64 + h * 16 + q], G[q * 128 + k], a);
            mv[r] = a;
        }
    }
    __syncthreads();
    #pragma unroll
    for (int r = 0; r < 8; r++) M[t + r * 512] = mv[r];
    __syncthreads();

    for (int g = t; g < OCH * 36; g += 512) {
        int o = g / 36, i0 = (g - o * 36) * 4;
        float a0 = 0.0f, a1 = 0.0f, a2 = 0.0f, a3 = 0.0f;
        const float* mo = M + o * 128;
        #pragma unroll 4
        for (int k = 0; k < 128; k++) {
            float mvv = mo[k];
            const float* wvr = &g_Wv[h][k][i0];
            a0 = fmaf(mvv, wvr[0], a0);
            a1 = fmaf(mvv, wvr[1], a1);
            a2 = fmaf(mvv, wvr[2], a2);
            a3 = fmaf(mvv, wvr[3], a3);
        }
        float* w2r = &g_W2[b][h][o][i0];
        w2r[0] = a0; w2r[1] = a1; w2r[2] = a2; w2r[3] = a3;
    }
}

// ---------------- kernel 5: fused output conv (f32x2) + BN stats ----------------
__global__ void __launch_bounds__(256) k_out(const float* __restrict__ cen, float* __restrict__ out) {
    extern __shared__ float dsm[];
    float* insm = dsm;
    float* W2sm = dsm + Cc * 3 * W2;

    int xg = blockIdx.x, b = blockIdx.y;
    int t = threadIdx.x;
    int ty = t & 31, to = t >> 5;
    const float* cb = cen + (size_t)b * Cc * NPIX;

    for (int xr = 0; xr < 4; xr++) {
        int x = xg * 4 + xr;
        ull acc2[4][3];
        #pragma unroll
        for (int oo = 0; oo < 4; oo++)
            #pragma unroll
            for (int j = 0; j < 3; j++) acc2[oo][j] = 0ull;

        for (int h = 0; h < Hh; h++) {
            int s = c_shift[h];
            int plen = HT + 2 * s;
            __syncthreads();
            for (int idx = t; idx < Cc * 3 * plen; idx += 256) {
                int c = idx / (3 * plen);
                int rem = idx - c * 3 * plen;
                int r = rem / plen;
                int p = rem - r * plen;
                int xx = x + (r - 1) * s;
                int y = p - s;
                float v = 0.0f;
                if (xx >= 0 && xx < WD && y >= 0 && y < HT)
                    v = cb[((size_t)c * WD + xx) * HT + y];
                insm[c * (3 * W2) + r * W2 + p] = v;
            }
            for (int idx = t; idx < OCH * SDIM; idx += 256)
                W2sm[idx] = (&g_W2[b][h][0][0])[idx];
            __syncthreads();

            int ybase = ty * 6;
            #pragma unroll 1
            for (int c = 0; c < Cc; c++) {
                const float* pc = insm + c * (3 * W2);
                #pragma unroll
                for (int d = 0; d < 9; d++) {
                    const float* px = pc + (d / 3) * W2 + (d % 3) * s + ybase;
                    float w0 = W2sm[(to * 4 + 0) * SDIM + c * 9 + d];
                    float w1 = W2sm[(to * 4 + 1) * SDIM + c * 9 + d];
                    float w2 = W2sm[(to * 4 + 2) * SDIM + c * 9 + d];
                    float w3 = W2sm[(to * 4 + 3) * SDIM + c * 9 + d];
                    ull w0p = pk2(w0, w0), w1p = pk2(w1, w1);
                    ull w2p = pk2(w2, w2), w3p = pk2(w3, w3);
                    #pragma unroll
                    for (int j = 0; j < 3; j++) {
                        ull xv = pk2(px[2 * j], px[2 * j + 1]);
                        acc2[0][j] = ffma2(w0p, xv, acc2[0][j]);
                        acc2[1][j] = ffma2(w1p, xv, acc2[1][j]);
                        acc2[2][j] = ffma2(w2p, xv, acc2[2][j]);
                        acc2[3][j] = ffma2(w3p, xv, acc2[3][j]);
                    }
                }
            }
        }

        #pragma unroll
        for (int oo = 0; oo < 4; oo++) {
            int o = to * 4 + oo;
            float s1 = 0.0f, s2 = 0.0f;
            float* op = out + (((size_t)b * OCH + o) * WD + x) * HT + ty * 6;
            #pragma unroll
            for (int j = 0; j < 3; j++) {
                float lo, hi;
                upk2(acc2[oo][j], lo, hi);
                op[2 * j]     = lo;
                op[2 * j + 1] = hi;
                s1 += lo + hi;
                s2 = fmaf(lo, lo, s2);
                s2 = fmaf(hi, hi, s2);
            }
            #pragma unroll
            for (int off2 = 16; off2 > 0; off2 >>= 1) {
                s1 += __shfl_xor_sync(0xffffffffu, s1, off2);
                s2 += __shfl_xor_sync(0xffffffffu, s2, off2);
            }
            if (ty == 0) {
                atomicAdd(&g_bnsum[o], s1);
                atomicAdd(&g_bnsq[o], s2);
            }
        }
    }
}

// ---------------- kernel 6: batchnorm + ReLU ----------------
__global__ void k_bn(float* __restrict__ out, const float* __restrict__ gamma,
                     const float* __restrict__ beta) {
    __shared__ float ssc[OCH], sbi[OCH];
    if (threadIdx.x < OCH) {
        int o = threadIdx.x;
        float invN = 1.0f / ((float)Bb * NPIX);
        float m = g_bnsum[o] * invN;
        float v = g_bnsq[o] * invN - m * m;
        float sc = gamma[o] * rsqrtf(v + 1e-5f);
        ssc[o] = sc;
        sbi[o] = beta[o] - m * sc;
    }
    __syncthreads();
    size_t total = (size_t)Bb * OCH * NPIX;
    for (size_t i = (size_t)blockIdx.x * blockDim.x + threadIdx.x; i < total;
         i += (size_t)gridDim.x * blockDim.x) {
        int o = (int)((i / NPIX) & 31);
        float v = fmaf(out[i], ssc[o], sbi[o]);
        out[i] = fmaxf(v, 0.0f);
    }
}

// ---------------- launch ----------------
extern "C" void kernel_launch(void* const* d_in, const int* in_sizes, int n_in,
                              void* d_out, int out_size) {
    (void)in_sizes; (void)n_in; (void)out_size;
    const float* cen   = (const float*)d_in[0];
    const float* wq    = (const float*)d_in[1];
    const float* wk    = (const float*)d_in[2];
    const float* wv    = (const float*)d_in[3];
    const float* sum_w = (const float*)d_in[4];
    const float* w_out = (const float*)d_in[5];
    const float* gamma = (const float*)d_in[6];
    const float* beta  = (const float*)d_in[7];
    float* out = (float*)d_out;

    int dynsmem_out    = (Cc * 3 * W2 + OCH * SDIM) * (int)sizeof(float);
    int dynsmem_attn   = 46096 * (int)sizeof(float);
    int dynsmem_stripx = 16 * 1121 * (int)sizeof(float);
    cudaFuncSetAttribute(k_out,    cudaFuncAttributeMaxDynamicSharedMemorySize, dynsmem_out);
    cudaFuncSetAttribute(k_attn,   cudaFuncAttributeMaxDynamicSharedMemorySize, dynsmem_attn);
    cudaFuncSetAttribute(k_stripx, cudaFuncAttributeMaxDynamicSharedMemorySize, dynsmem_stripx);

    k_prep<<<4, 256>>>(wq, wk, wv, sum_w);
    k_zero<<<512, 256>>>();
    k_corrF<<<dim3(8, 4, 8), 256>>>(cen);
    k_stripx<<<dim3(8, 4, 8), 256, dynsmem_stripx>>>(cen);
    k_stripy<<<dim3(8, 4, 8), 256>>>(cen);
    k_corner<<<dim3(4, 4, 8), 256>>>(cen);
    k_mirrorF<<<32, 256>>>();
    k_attn<<<32, 512, dynsmem_attn>>>(w_out);
    k_out<<<dim3(48, 8), 256, dynsmem_out>>>(cen, out);
    k_bn<<<2048, 256>>>(out, gamma, beta);
}

// round 9
// speedup vs baseline: 1.7497x; 1.0826x over previous
#include <cuda_runtime.h>
#include <math.h>

#define Bb 8
#define Cc 16
#define WD 192
#define HT 192
#define NPIX (WD*HT)
#define Hh 4
#define HID 16
#define OCH 32
#define W2 214
#define SDIM 144

typedef unsigned long long ull;

// ---------------- packed f32x2 helpers (k_out) ----------------
__device__ __forceinline__ ull pk2(float lo, float hi) {
    ull u;
    asm("mov.b64 %0, {%1, %2};" : "=l"(u) : "f"(lo), "f"(hi));
    return u;
}
__device__ __forceinline__ void upk2(ull u, float& lo, float& hi) {
    asm("mov.b64 {%0, %1}, %2;" : "=f"(lo), "=f"(hi) : "l"(u));
}
__device__ __forceinline__ ull ffma2(ull a, ull b, ull c) {
    ull d;
    asm("fma.rn.f32x2 %0, %1, %2, %3;" : "=l"(d) : "l"(a), "l"(b), "l"(c));
    return d;
}

// ---------------- device scratch ----------------
__device__ float g_Wq[Hh][HID][SDIM];
__device__ float g_Wk[Hh][128][SDIM];
__device__ float g_Wv[Hh][128][SDIM];
__device__ float g_W2[Bb][Hh][OCH][SDIM];
__device__ float g_bnsum[OCH];
__device__ float g_bnsq[OCH];

// correlation tables: [bh][pair=c1*16+c2][lag dd=ix*5+iy], ix=dx/s+2, iy=dy/s+2
__device__ float g_F [32][256][25];
__device__ float g_SxS[2][32][256][25];   // [0]=low-x strip (qx in [0,s)), [1]=high-x
__device__ float g_SyS[2][32][256][25];   // [0]=low-y, [1]=high-y
__device__ float g_Cn [4][32][256][25];   // [cx*2+cy], cx/cy: 0=low,1=high

__constant__ int c_shift[4] = {1, 2, 4, 8};
__constant__ int c_off[8]   = {0, 1, 2, 5, 8, 7, 6, 3};

// ---------------- kernel 1: fold blend kernels into effective conv weights ----------------
__global__ void k_prep(const float* __restrict__ wq, const float* __restrict__ wk,
                       const float* __restrict__ wv, const float* __restrict__ sum_w) {
    int h = blockIdx.x;
    int t = threadIdx.x;
    __shared__ float wcen[Cc][9];
    __shared__ float wsur[Cc][8][9];

    if (t < Cc * 9) {
        int c = t / 9, d = t % 9;
        float sw = sum_w[h * Cc + c];
        float su_f = (d == 4) ? 0.125f : (7.0f / 64.0f);
        float ce   = (d == 4) ? 1.0f : 0.0f;
        wcen[c][d] = su_f * (1.0f - sw) + ce * sw;
    }
    for (int idx = t; idx < Cc * 8 * 9; idx += 256) {
        int c = idx / 72;
        int k = (idx / 9) % 8;
        int d = idx % 9;
        float sw = sum_w[h * Cc + c];
        float delta = ((d == 4) ? 1.0f : 0.0f) + ((d == c_off[k]) ? -1.0f : 0.0f);
        float ce    = (d == 4) ? 1.0f : 0.0f;
        float k2w   = (delta - ce) * 1.125f + 0.125f;
        wsur[c][k][d] = delta * (1.0f - sw) + k2w * sw;
    }
    __syncthreads();

    for (int idx = t; idx < HID * SDIM; idx += 256) {
        int q = idx / SDIM, c = (idx % SDIM) / 9, d = idx % 9;
        g_Wq[h][q][c * 9 + d] = wq[(h * HID + q) * Cc + c] * wcen[c][d];
    }
    for (int idx = t; idx < 128 * SDIM; idx += 256) {
        int o = idx / SDIM, c = (idx % SDIM) / 9, d = idx % 9;
        float ak = 0.0f, av = 0.0f;
        #pragma unroll
        for (int k = 0; k < 8; k++) {
            float ws = wsur[c][k][d];
            ak = fmaf(wk[(h * 128 + o) * 128 + k * Cc + c], ws, ak);
            av = fmaf(wv[(h * 128 + o) * 128 + k * Cc + c], ws, av);
        }
        g_Wk[h][o][c * 9 + d] = ak;
        g_Wv[h][o][c * 9 + d] = av;
    }
}

// ---------------- kernel 2: zero accumulators ----------------
__global__ void k_zero() {
    const long per = 32L * 256 * 25;
    long stride = (long)gridDim.x * 256;
    long i0 = (long)blockIdx.x * 256 + threadIdx.x;
    for (long i = i0; i < per; i += stride) (&g_F[0][0][0])[i] = 0.0f;
    for (long i = i0; i < 2 * per; i += stride) (&g_SxS[0][0][0][0])[i] = 0.0f;
    for (long i = i0; i < 2 * per; i += stride) (&g_SyS[0][0][0][0])[i] = 0.0f;
    if (blockIdx.x == 0 && threadIdx.x < OCH) {
        g_bnsum[threadIdx.x] = 0.0f;
        g_bnsq[threadIdx.x]  = 0.0f;
    }
}

// ---------------- kernel 3a: full-domain correlations F(dd) for dd=12..24 ----------------
// grid (8 x-chunks of 24 rows, Hh, Bb), 256 threads:
//   c2 = t&15, c1-group = (t>>4)&3 (4 c1 each), qy-quarter = t>>6 (48 qy each).
// Register tile: 4 c1 x 13 lags -> 17 LDS per 52 FMA (FMA-bound).
__global__ void __launch_bounds__(256) k_corrF(const float* __restrict__ cen) {
    __shared__ float st[16 * 673];
    int xc = blockIdx.x, h = blockIdx.y, b = blockIdx.z;
    int s = c_shift[h];
    int bh = b * Hh + h;
    int t = threadIdx.x;
    int c2 = t & 15;
    int c1b = ((t >> 4) & 3) * 4;
    int qq = t >> 6;
    const float* cb = cen + (size_t)b * Cc * NPIX;

    float acc[52];
    #pragma unroll
    for (int i = 0; i < 52; i++) acc[i] = 0.0f;

    for (int qx = xc * 24; qx < xc * 24 + 24; qx++) {
        __syncthreads();
        for (int idx = t; idx < 16 * 673; idx += 256) {
            int c = idx / 673;
            int rm = idx - c * 673;
            float v = 0.0f;
            if (rm < 672) {
                int k = rm / 224, j = rm - k * 224;
                int r = qx + k * s;
                int y = j - 16;
                if (r < WD && y >= 0 && y < HT)
                    v = cb[((size_t)c * WD + r) * HT + y];
            }
            st[idx] = v;
        }
        __syncthreads();

        const float* a0 = st + (c1b + 0) * 673 + 16;
        const float* a1 = st + (c1b + 1) * 673 + 16;
        const float* a2 = st + (c1b + 2) * 673 + 16;
        const float* a3 = st + (c1b + 3) * 673 + 16;
        const float* b0 = st + c2 * 673 + 16;
        const float* b1 = b0 + 224;
        const float* b2 = b1 + 224;
        #pragma unroll 2
        for (int qy = qq * 48; qy < qq * 48 + 48; qy++) {
            float av0 = a0[qy], av1 = a1[qy], av2 = a2[qy], av3 = a3[qy];
            float bv;
            #define CORR_LAG(L, EXPR) \
                bv = (EXPR); \
                acc[0 * 13 + (L)] = fmaf(av0, bv, acc[0 * 13 + (L)]); \
                acc[1 * 13 + (L)] = fmaf(av1, bv, acc[1 * 13 + (L)]); \
                acc[2 * 13 + (L)] = fmaf(av2, bv, acc[2 * 13 + (L)]); \
                acc[3 * 13 + (L)] = fmaf(av3, bv, acc[3 * 13 + (L)]);
            CORR_LAG(0,  b0[qy])
            CORR_LAG(1,  b0[qy + s])
            CORR_LAG(2,  b0[qy + 2 * s])
            CORR_LAG(3,  b1[qy - 2 * s])
            CORR_LAG(4,  b1[qy - s])
            CORR_LAG(5,  b1[qy])
            CORR_LAG(6,  b1[qy + s])
            CORR_LAG(7,  b1[qy + 2 * s])
            CORR_LAG(8,  b2[qy - 2 * s])
            CORR_LAG(9,  b2[qy - s])
            CORR_LAG(10, b2[qy])
            CORR_LAG(11, b2[qy + s])
            CORR_LAG(12, b2[qy + 2 * s])
            #undef CORR_LAG
        }
    }
    #pragma unroll
    for (int i = 0; i < 4; i++) {
        float* dst = &g_F[bh][(c1b + i) * 16 + c2][12];
        #pragma unroll
        for (int l = 0; l < 13; l++) atomicAdd(dst + l, acc[i * 13 + l]);
    }
}

// ---------------- kernel 3b: x-border strips, all 25 lags (80-wide y windows) ----------------
// grid (8 = side(2) x ychunk(4), Hh, Bb); strip qx in [x0, x0+s), qy in chunk of 48.
__global__ void __launch_bounds__(256) k_stripx(const float* __restrict__ cen) {
    __shared__ float yw[16 * 401];    // 5 x-rows x 80 y per channel, stride 401
    int side = blockIdx.x & 1, chunk = blockIdx.x >> 1;
    int h = blockIdx.y, b = blockIdx.z;
    int s = c_shift[h];
    int bh = b * Hh + h;
    int t = threadIdx.x;
    int c1 = t & 15, c2 = t >> 4;
    const float* cb = cen + (size_t)b * Cc * NPIX;
    int x0 = side ? (WD - s) : 0;
    int ybase = chunk * 48 - 16;

    float acc[25];
    #pragma unroll
    for (int i = 0; i < 25; i++) acc[i] = 0.0f;

    for (int qq = 0; qq < s; qq++) {
        int qx = x0 + qq;
        __syncthreads();
        for (int idx = t; idx < 16 * 401; idx += 256) {
            int c = idx / 401;
            int rm = idx - c * 401;
            float v = 0.0f;
            if (rm < 400) {
                int k = rm / 80, j = rm - k * 80;
                int r = qx + (k - 2) * s;
                int y = ybase + j;
                if (r >= 0 && r < WD && y >= 0 && y < HT)
                    v = cb[((size_t)c * WD + r) * HT + y];
            }
            yw[idx] = v;
        }
        __syncthreads();

        const float* ar = yw + c1 * 401 + 2 * 80 + 16;
        const float* bb = yw + c2 * 401 + 16;
        for (int jj = 0; jj < 48; jj++) {
            float a = ar[jj];
            #pragma unroll
            for (int ix = 0; ix < 5; ix++) {
                const float* br = bb + ix * 80 + jj;
                #pragma unroll
                for (int iy = 0; iy < 5; iy++)
                    acc[ix * 5 + iy] = fmaf(a, br[(iy - 2) * s], acc[ix * 5 + iy]);
            }
        }
    }
    float* dst = &g_SxS[side][bh][c1 * 16 + c2][0];
    #pragma unroll
    for (int i = 0; i < 25; i++) atomicAdd(dst + i, acc[i]);
}

// ---------------- kernel 3c: y-border strips, all 25 lags (5s-wide y windows) ----------------
// grid (8 = side(2) x xchunk(4), Hh, Bb); strip qy in [y0, y0+s), qx in chunk of 48.
__global__ void __launch_bounds__(256) k_stripy(const float* __restrict__ cen) {
    __shared__ float yw[16 * 201];
    int side = blockIdx.x & 1, chunk = blockIdx.x >> 1;
    int h = blockIdx.y, b = blockIdx.z;
    int s = c_shift[h];
    int bh = b * Hh + h;
    int t = threadIdx.x;
    int c1 = t & 15, c2 = t >> 4;
    const float* cb = cen + (size_t)b * Cc * NPIX;
    int y0 = side ? (HT - s) : 0;
    int jy0 = y0 - 2 * s;
    int ww = 5 * s;                 // y-window width
    int stride = 5 * ww + 1;        // per-channel smem stride (5 x-rows)
    int tot = 16 * stride;

    float acc[25];
    #pragma unroll
    for (int i = 0; i < 25; i++) acc[i] = 0.0f;

    for (int qx = chunk * 48; qx < chunk * 48 + 48; qx++) {
        __syncthreads();
        for (int idx = t; idx < tot; idx += 256) {
            int c = idx / stride;
            int rm = idx - c * stride;
            float v = 0.0f;
            if (rm < 5 * ww) {
                int k = rm / ww, j = rm - k * ww;
                int r = qx + (k - 2) * s;
                int y = jy0 + j;
                if (r >= 0 && r < WD && y >= 0 && y < HT)
                    v = cb[((size_t)c * WD + r) * HT + y];
            }
            yw[idx] = v;
        }
        __syncthreads();

        const float* ar = yw + c1 * stride + 2 * ww + 2 * s;
        const float* bb = yw + c2 * stride;
        for (int jj = 0; jj < s; jj++) {
            float a = ar[jj];
            #pragma unroll
            for (int ix = 0; ix < 5; ix++) {
                const float* br = bb + ix * ww + jj;
                #pragma unroll
                for (int iy = 0; iy < 5; iy++)
                    acc[ix * 5 + iy] = fmaf(a, br[iy * s], acc[ix * 5 + iy]);
            }
        }
    }
    float* dst = &g_SyS[side][bh][c1 * 16 + c2][0];
    #pragma unroll
    for (int i = 0; i < 25; i++) atomicAdd(dst + i, acc[i]);
}

// ---------------- kernel 3d: s x s corner patches, all 25 lags ----------------
__global__ void __launch_bounds__(256) k_corner(const float* __restrict__ cen) {
    int corner = blockIdx.x;
    int cx = corner >> 1, cy = corner & 1;
    int h = blockIdx.y, b = blockIdx.z;
    int s = c_shift[h];
    int bh = b * Hh + h;
    int t = threadIdx.x;
    int c1 = t & 15, c2 = t >> 4;
    const float* cb = cen + (size_t)b * Cc * NPIX;
    int x0 = cx ? (WD - s) : 0;
    int y0 = cy ? (HT - s) : 0;

    float acc[25];
    #pragma unroll
    for (int i = 0; i < 25; i++) acc[i] = 0.0f;

    for (int i = 0; i < s; i++) {
        for (int j = 0; j < s; j++) {
            int qx = x0 + i, qy = y0 + j;
            float a = cb[((size_t)c1 * WD + qx) * HT + qy];
            #pragma unroll
            for (int ix = 0; ix < 5; ix++) {
                int bx = qx + (ix - 2) * s;
                #pragma unroll
                for (int iy = 0; iy < 5; iy++) {
                    int by = qy + (iy - 2) * s;
                    float bv = (bx >= 0 && bx < WD && by >= 0 && by < HT)
                               ? cb[((size_t)c2 * WD + bx) * HT + by] : 0.0f;
                    acc[ix * 5 + iy] = fmaf(a, bv, acc[ix * 5 + iy]);
                }
            }
        }
    }
    float* dst = &g_Cn[corner][bh][c1 * 16 + c2][0];
    #pragma unroll
    for (int i = 0; i < 25; i++) dst[i] = acc[i];
}

// ---------------- kernel 3e: mirror fill F for dd<12 ----------------
__global__ void k_mirrorF() {
    int bh = blockIdx.x;
    int p = threadIdx.x;
    int cA = p >> 4, cB = p & 15;
    int ps = cB * 16 + cA;
    #pragma unroll
    for (int d = 0; d < 12; d++)
        g_F[bh][p][d] = g_F[bh][ps][24 - d];
}

// ---------------- kernel 4: per (b,h) attention head (assembles S from corr tables) ----------------
__global__ void __launch_bounds__(512) k_attn(const float* __restrict__ w_out) {
    extern __shared__ float pool[];
    float* S_sm  = pool;
    float* Wk_sm = pool + 20880;
    float* Wq_sm = pool + 39440;
    float* T_sm  = pool + 41744;
    float* G     = pool + 44048;
    float* M     = Wk_sm;
    __shared__ float nq[16], nk[128], red[512];

    int bh = blockIdx.x;
    int b = bh >> 2, h = bh & 3;
    int t = threadIdx.x;

    for (int idx = t; idx < SDIM * SDIM; idx += 512) {
        int r = idx / SDIM, c = idx - r * SDIM;
        int c1 = r / 9, d1 = r - c1 * 9;
        int c2 = c / 9, d2 = c - c2 * 9;
        int o1x = d1 / 3 - 1, o1y = d1 % 3 - 1;
        int o2x = d2 / 3 - 1, o2y = d2 % 3 - 1;
        int dd = (o2x - o1x + 2) * 5 + (o2y - o1y + 2);
        int p = c1 * 16 + c2;
        float v = g_F[bh][p][dd];
        if (o1x > 0)      v -= g_SxS[0][bh][p][dd];
        else if (o1x < 0) v -= g_SxS[1][bh][p][dd];
        if (o1y > 0)      v -= g_SyS[0][bh][p][dd];
        else if (o1y < 0) v -= g_SyS[1][bh][p][dd];
        if (o1x != 0 && o1y != 0) {
            int ci = ((o1x > 0) ? 0 : 2) + ((o1y > 0) ? 0 : 1);
            v += g_Cn[ci][bh][p][dd];
        }
        S_sm[r * 145 + c] = v;
    }
    for (int idx = t; idx < 128 * SDIM; idx += 512) {
        int r = idx / SDIM, c = idx - r * SDIM;
        Wk_sm[r * 145 + c] = (&g_Wk[h][0][0])[idx];
    }
    for (int idx = t; idx < 16 * SDIM; idx += 512)
        Wq_sm[idx] = (&g_Wq[h][0][0])[idx];
    __syncthreads();

    for (int g = t; g < 576; g += 512) {
        int q = g / 36, i0 = (g - q * 36) * 4;
        float a0 = 0.0f, a1 = 0.0f, a2 = 0.0f, a3 = 0.0f;
        const float* wqr = Wq_sm + q * SDIM;
        #pragma unroll 4
        for (int j = 0; j < SDIM; j++) {
            float wv = wqr[j];
            const float* sr = S_sm + j * 145 + i0;
            a0 = fmaf(wv, sr[0], a0);
            a1 = fmaf(wv, sr[1], a1);
            a2 = fmaf(wv, sr[2], a2);
            a3 = fmaf(wv, sr[3], a3);
        }
        float* tr = T_sm + q * SDIM + i0;
        tr[0] = a0; tr[1] = a1; tr[2] = a2; tr[3] = a3;
    }
    __syncthreads();

    if (t < 16) {
        float a = 0.0f;
        for (int i = 0; i < SDIM; i++)
            a = fmaf(T_sm[t * SDIM + i], Wq_sm[t * SDIM + i], a);
        nq[t] = fmaxf(sqrtf(fmaxf(a, 0.0f)), 1e-12f);
    }

    {
        int q = t >> 5, k0 = (t & 31) * 4;
        float a0 = 0.0f, a1 = 0.0f, a2 = 0.0f, a3 = 0.0f;
        const float* tq = T_sm + q * SDIM;
        const float* w0 = Wk_sm + (k0 + 0) * 145;
        const float* w1 = Wk_sm + (k0 + 1) * 145;
        const float* w2 = Wk_sm + (k0 + 2) * 145;
        const float* w3 = Wk_sm + (k0 + 3) * 145;
        #pragma unroll 4
        for (int i = 0; i < SDIM; i++) {
            float tv = tq[i];
            a0 = fmaf(tv, w0[i], a0);
            a1 = fmaf(tv, w1[i], a1);
            a2 = fmaf(tv, w2[i], a2);
            a3 = fmaf(tv, w3[i], a3);
        }
        G[q * 128 + k0 + 0] = a0;
        G[q * 128 + k0 + 1] = a1;
        G[q * 128 + k0 + 2] = a2;
        G[q * 128 + k0 + 3] = a3;
    }

    {
        int k = t & 127, g = t >> 7;
        const float* wk_r = Wk_sm + k * 145;
        float a = 0.0f;
        #pragma unroll 1
        for (int qd = 0; qd < 9; qd++) {
            int i0 = g * 36 + qd * 4;
            float r0 = 0.0f, r1 = 0.0f, r2 = 0.0f, r3 = 0.0f;
            const float* s0 = S_sm + (i0 + 0) * 145;
            const float* s1 = S_sm + (i0 + 1) * 145;
            const float* s2 = S_sm + (i0 + 2) * 145;
            const float* s3 = S_sm + (i0 + 3) * 145;
            #pragma unroll 4
            for (int j = 0; j < SDIM; j++) {
                float wv = wk_r[j];
                r0 = fmaf(s0[j], wv, r0);
                r1 = fmaf(s1[j], wv, r1);
                r2 = fmaf(s2[j], wv, r2);
                r3 = fmaf(s3[j], wv, r3);
            }
            a = fmaf(wk_r[i0 + 0], r0, a);
            a = fmaf(wk_r[i0 + 1], r1, a);
            a = fmaf(wk_r[i0 + 2], r2, a);
            a = fmaf(wk_r[i0 + 3], r3, a);
        }
        red[t] = a;
    }
    __syncthreads();
    if (t < 128) {
        float sum = red[t] + red[t + 128] + red[t + 256] + red[t + 384];
        nk[t] = fmaxf(sqrtf(fmaxf(sum, 0.0f)), 1e-12f);
    }
    __syncthreads();

    for (int idx = t; idx < 2048; idx += 512) {
        int q = idx >> 7, k = idx & 127;
        G[idx] = G[idx] / (nq[q] * nk[k] * 192.0f);
    }
    __syncthreads();

    float lsum = 0.0f;
    for (int idx = t; idx < 2048; idx += 512) lsum += G[idx];
    red[t] = lsum; __syncthreads();
    for (int st = 256; st > 0; st >>= 1) { if (t < st) red[t] += red[t + st]; __syncthreads(); }
    float mean = red[0] * (1.0f / 2048.0f);
    __syncthreads();
    float lss = 0.0f;
    for (int idx = t; idx < 2048; idx += 512) { float d = G[idx] - mean; lss = fmaf(d, d, lss); }
    red[t] = lss; __syncthreads();
    for (int st = 256; st > 0; st >>= 1) { if (t < st) red[t] += red[t + st]; __syncthreads(); }
    float var = red[0] * (1.0f / 2048.0f);
    float iscale = rsqrtf(var + 1e-5f);
    __syncthreads();
    for (int idx = t; idx < 2048; idx += 512)
        G[idx] = (G[idx] - mean) * iscale;
    __syncthreads();

    int wid = t >> 5, lane = t & 31;
    {
        int q = wid;
        float m = -1e30f;
        for (int k = lane; k < 128; k += 32) m = fmaxf(m, G[q * 128 + k]);
        #pragma unroll
        for (int o = 16; o > 0; o >>= 1) m = fmaxf(m, __shfl_xor_sync(0xffffffffu, m, o));
        float ssum = 0.0f;
        for (int k = lane; k < 128; k += 32) {
            float e = expf(G[q * 128 + k] - m);
            G[q * 128 + k] = e;
            ssum += e;
        }
        #pragma unroll
        for (int o = 16; o > 0; o >>= 1) ssum += __shfl_xor_sync(0xffffffffu, ssum, o);
        float inv = 1.0f / ssum;
        for (int k = lane; k < 128; k += 32) G[q * 128 + k] *= inv;
    }
    __syncthreads();

    float mv[8];
    {
        #pragma unroll
        for (int r = 0; r < 8; r++) {
            int idx = t + r * 512;
            int o = idx >> 7, k = idx & 127;
            float a = 0.0f;
            #pragma unroll
            for (int q = 0; q < 16; q++)
                a = fmaf(w_out[o * 64 + h * 16 + q], G[q * 128 + k], a);
            mv[r] = a;
        }
    }
    __syncthreads();
    #pragma unroll
    for (int r = 0; r < 8; r++) M[t + r * 512] = mv[r];
    __syncthreads();

    for (int g = t; g < OCH * 36; g += 512) {
        int o = g / 36, i0 = (g - o * 36) * 4;
        float a0 = 0.0f, a1 = 0.0f, a2 = 0.0f, a3 = 0.0f;
        const float* mo = M + o * 128;
        #pragma unroll 4
        for (int k = 0; k < 128; k++) {
            float mvv = mo[k];
            const float* wvr = &g_Wv[h][k][i0];
            a0 = fmaf(mvv, wvr[0], a0);
            a1 = fmaf(mvv, wvr[1], a1);
            a2 = fmaf(mvv, wvr[2], a2);
            a3 = fmaf(mvv, wvr[3], a3);
        }
        float* w2r = &g_W2[b][h][o][i0];
        w2r[0] = a0; w2r[1] = a1; w2r[2] = a2; w2r[3] = a3;
    }
}

// ---------------- kernel 5: fused output conv (f32x2) + BN stats ----------------
__global__ void __launch_bounds__(256) k_out(const float* __restrict__ cen, float* __restrict__ out) {
    extern __shared__ float dsm[];
    float* insm = dsm;
    float* W2sm = dsm + Cc * 3 * W2;

    int xg = blockIdx.x, b = blockIdx.y;
    int t = threadIdx.x;
    int ty = t & 31, to = t >> 5;
    const float* cb = cen + (size_t)b * Cc * NPIX;

    for (int xr = 0; xr < 4; xr++) {
        int x = xg * 4 + xr;
        ull acc2[4][3];
        #pragma unroll
        for (int oo = 0; oo < 4; oo++)
            #pragma unroll
            for (int j = 0; j < 3; j++) acc2[oo][j] = 0ull;

        for (int h = 0; h < Hh; h++) {
            int s = c_shift[h];
            int plen = HT + 2 * s;
            __syncthreads();
            for (int idx = t; idx < Cc * 3 * plen; idx += 256) {
                int c = idx / (3 * plen);
                int rem = idx - c * 3 * plen;
                int r = rem / plen;
                int p = rem - r * plen;
                int xx = x + (r - 1) * s;
                int y = p - s;
                float v = 0.0f;
                if (xx >= 0 && xx < WD && y >= 0 && y < HT)
                    v = cb[((size_t)c * WD + xx) * HT + y];
                insm[c * (3 * W2) + r * W2 + p] = v;
            }
            for (int idx = t; idx < OCH * SDIM; idx += 256)
                W2sm[idx] = (&g_W2[b][h][0][0])[idx];
            __syncthreads();

            int ybase = ty * 6;
            #pragma unroll 1
            for (int c = 0; c < Cc; c++) {
                const float* pc = insm + c * (3 * W2);
                #pragma unroll
                for (int d = 0; d < 9; d++) {
                    const float* px = pc + (d / 3) * W2 + (d % 3) * s + ybase;
                    float w0 = W2sm[(to * 4 + 0) * SDIM + c * 9 + d];
                    float w1 = W2sm[(to * 4 + 1) * SDIM + c * 9 + d];
                    float w2 = W2sm[(to * 4 + 2) * SDIM + c * 9 + d];
                    float w3 = W2sm[(to * 4 + 3) * SDIM + c * 9 + d];
                    ull w0p = pk2(w0, w0), w1p = pk2(w1, w1);
                    ull w2p = pk2(w2, w2), w3p = pk2(w3, w3);
                    #pragma unroll
                    for (int j = 0; j < 3; j++) {
                        ull xv = pk2(px[2 * j], px[2 * j + 1]);
                        acc2[0][j] = ffma2(w0p, xv, acc2[0][j]);
                        acc2[1][j] = ffma2(w1p, xv, acc2[1][j]);
                        acc2[2][j] = ffma2(w2p, xv, acc2[2][j]);
                        acc2[3][j] = ffma2(w3p, xv, acc2[3][j]);
                    }
                }
            }
        }

        #pragma unroll
        for (int oo = 0; oo < 4; oo++) {
            int o = to * 4 + oo;
            float s1 = 0.0f, s2 = 0.0f;
            float* op = out + (((size_t)b * OCH + o) * WD + x) * HT + ty * 6;
            #pragma unroll
            for (int j = 0; j < 3; j++) {
                float lo, hi;
                upk2(acc2[oo][j], lo, hi);
                op[2 * j]     = lo;
                op[2 * j + 1] = hi;
                s1 += lo + hi;
                s2 = fmaf(lo, lo, s2);
                s2 = fmaf(hi, hi, s2);
            }
            #pragma unroll
            for (int off2 = 16; off2 > 0; off2 >>= 1) {
                s1 += __shfl_xor_sync(0xffffffffu, s1, off2);
                s2 += __shfl_xor_sync(0xffffffffu, s2, off2);
            }
            if (ty == 0) {
                atomicAdd(&g_bnsum[o], s1);
                atomicAdd(&g_bnsq[o], s2);
            }
        }
    }
}

// ---------------- kernel 6: batchnorm + ReLU ----------------
__global__ void k_bn(float* __restrict__ out, const float* __restrict__ gamma,
                     const float* __restrict__ beta) {
    __shared__ float ssc[OCH], sbi[OCH];
    if (threadIdx.x < OCH) {
        int o = threadIdx.x;
        float invN = 1.0f / ((float)Bb * NPIX);
        float m = g_bnsum[o] * invN;
        float v = g_bnsq[o] * invN - m * m;
        float sc = gamma[o] * rsqrtf(v + 1e-5f);
        ssc[o] = sc;
        sbi[o] = beta[o] - m * sc;
    }
    __syncthreads();
    size_t total = (size_t)Bb * OCH * NPIX;
    for (size_t i = (size_t)blockIdx.x * blockDim.x + threadIdx.x; i < total;
         i += (size_t)gridDim.x * blockDim.x) {
        int o = (int)((i / NPIX) & 31);
        float v = fmaf(out[i], ssc[o], sbi[o]);
        out[i] = fmaxf(v, 0.0f);
    }
}

// ---------------- launch ----------------
extern "C" void kernel_launch(void* const* d_in, const int* in_sizes, int n_in,
                              void* d_out, int out_size) {
    (void)in_sizes; (void)n_in; (void)out_size;
    const float* cen   = (const float*)d_in[0];
    const float* wq    = (const float*)d_in[1];
    const float* wk    = (const float*)d_in[2];
    const float* wv    = (const float*)d_in[3];
    const float* sum_w = (const float*)d_in[4];
    const float* w_out = (const float*)d_in[5];
    const float* gamma = (const float*)d_in[6];
    const float* beta  = (const float*)d_in[7];
    float* out = (float*)d_out;

    int dynsmem_out  = (Cc * 3 * W2 + OCH * SDIM) * (int)sizeof(float);
    int dynsmem_attn = 46096 * (int)sizeof(float);
    cudaFuncSetAttribute(k_out,  cudaFuncAttributeMaxDynamicSharedMemorySize, dynsmem_out);
    cudaFuncSetAttribute(k_attn, cudaFuncAttributeMaxDynamicSharedMemorySize, dynsmem_attn);

    k_prep<<<4, 256>>>(wq, wk, wv, sum_w);
    k_zero<<<512, 256>>>();
    k_corrF<<<dim3(8, 4, 8), 256>>>(cen);
    k_stripx<<<dim3(8, 4, 8), 256>>>(cen);
    k_stripy<<<dim3(8, 4, 8), 256>>>(cen);
    k_corner<<<dim3(4, 4, 8), 256>>>(cen);
    k_mirrorF<<<32, 256>>>();
    k_attn<<<32, 512, dynsmem_attn>>>(w_out);
    k_out<<<dim3(48, 8), 256, dynsmem_out>>>(cen, out);
    k_bn<<<2048, 256>>>(out, gamma, beta);
}

// round 10
// speedup vs baseline: 2.1069x; 1.2042x over previous
#include <cuda_runtime.h>
#include <math.h>

#define Bb 8
#define Cc 16
#define WD 192
#define HT 192
#define NPIX (WD*HT)
#define Hh 4
#define HID 16
#define OCH 32
#define W2 214
#define SDIM 144

typedef unsigned long long ull;

// ---------------- packed f32x2 helpers (k_out) ----------------
__device__ __forceinline__ ull pk2(float lo, float hi) {
    ull u;
    asm("mov.b64 %0, {%1, %2};" : "=l"(u) : "f"(lo), "f"(hi));
    return u;
}
__device__ __forceinline__ void upk2(ull u, float& lo, float& hi) {
    asm("mov.b64 {%0, %1}, %2;" : "=f"(lo), "=f"(hi) : "l"(u));
}
__device__ __forceinline__ ull ffma2(ull a, ull b, ull c) {
    ull d;
    asm("fma.rn.f32x2 %0, %1, %2, %3;" : "=l"(d) : "l"(a), "l"(b), "l"(c));
    return d;
}

// ---------------- device scratch ----------------
__device__ float g_Wq[Hh][HID][SDIM];
__device__ float g_Wk[Hh][128][SDIM];
__device__ float g_Wv[Hh][128][SDIM];
__device__ float g_W2[Bb][Hh][OCH][SDIM];
__device__ float g_bnsum[OCH];
__device__ float g_bnsq[OCH];

// correlation tables: [bh][pair=c1*16+c2][lag dd=ix*5+iy], ix=dx/s+2, iy=dy/s+2
__device__ float g_F [32][256][25];
__device__ float g_SxS[2][32][256][25];   // [0]=low-x strip (qx in [0,s)), [1]=high-x
__device__ float g_SyS[2][32][256][25];   // [0]=low-y, [1]=high-y
__device__ float g_Cn [4][32][256][25];   // [cx*2+cy], cx/cy: 0=low,1=high

__constant__ int c_shift[4] = {1, 2, 4, 8};
__constant__ int c_off[8]   = {0, 1, 2, 5, 8, 7, 6, 3};

// ---------------- kernel 1: fold blend kernels into effective conv weights ----------------
__global__ void k_prep(const float* __restrict__ wq, const float* __restrict__ wk,
                       const float* __restrict__ wv, const float* __restrict__ sum_w) {
    int h = blockIdx.x;
    int t = threadIdx.x;
    __shared__ float wcen[Cc][9];
    __shared__ float wsur[Cc][8][9];

    if (t < Cc * 9) {
        int c = t / 9, d = t % 9;
        float sw = sum_w[h * Cc + c];
        float su_f = (d == 4) ? 0.125f : (7.0f / 64.0f);
        float ce   = (d == 4) ? 1.0f : 0.0f;
        wcen[c][d] = su_f * (1.0f - sw) + ce * sw;
    }
    for (int idx = t; idx < Cc * 8 * 9; idx += 256) {
        int c = idx / 72;
        int k = (idx / 9) % 8;
        int d = idx % 9;
        float sw = sum_w[h * Cc + c];
        float delta = ((d == 4) ? 1.0f : 0.0f) + ((d == c_off[k]) ? -1.0f : 0.0f);
        float ce    = (d == 4) ? 1.0f : 0.0f;
        float k2w   = (delta - ce) * 1.125f + 0.125f;
        wsur[c][k][d] = delta * (1.0f - sw) + k2w * sw;
    }
    __syncthreads();

    for (int idx = t; idx < HID * SDIM; idx += 256) {
        int q = idx / SDIM, c = (idx % SDIM) / 9, d = idx % 9;
        g_Wq[h][q][c * 9 + d] = wq[(h * HID + q) * Cc + c] * wcen[c][d];
    }
    for (int idx = t; idx < 128 * SDIM; idx += 256) {
        int o = idx / SDIM, c = (idx % SDIM) / 9, d = idx % 9;
        float ak = 0.0f, av = 0.0f;
        #pragma unroll
        for (int k = 0; k < 8; k++) {
            float ws = wsur[c][k][d];
            ak = fmaf(wk[(h * 128 + o) * 128 + k * Cc + c], ws, ak);
            av = fmaf(wv[(h * 128 + o) * 128 + k * Cc + c], ws, av);
        }
        g_Wk[h][o][c * 9 + d] = ak;
        g_Wv[h][o][c * 9 + d] = av;
    }
}

// ---------------- kernel 2: zero accumulators ----------------
__global__ void k_zero() {
    const long per = 32L * 256 * 25;
    long stride = (long)gridDim.x * 256;
    long i0 = (long)blockIdx.x * 256 + threadIdx.x;
    for (long i = i0; i < per; i += stride) (&g_F[0][0][0])[i] = 0.0f;
    for (long i = i0; i < 2 * per; i += stride) (&g_SxS[0][0][0][0])[i] = 0.0f;
    for (long i = i0; i < 2 * per; i += stride) (&g_SyS[0][0][0][0])[i] = 0.0f;
    for (long i = i0; i < 4 * per; i += stride) (&g_Cn[0][0][0][0])[i] = 0.0f;
    if (blockIdx.x == 0 && threadIdx.x < OCH) {
        g_bnsum[threadIdx.x] = 0.0f;
        g_bnsq[threadIdx.x]  = 0.0f;
    }
}

// ---------------- kernel 3a: full-domain correlations F(dd) for dd=12..24 ----------------
// grid (24 x-chunks of 8 rows, Hh, Bb), 256 threads:
//   c2 = t&15, c1-group = (t>>4)&3 (4 c1 each), qy-quarter = t>>6 (48 qy each).
// Register tile: 4 c1 x 13 lags -> 17 LDS per 52 FMA (FMA-bound).
__global__ void __launch_bounds__(256) k_corrF(const float* __restrict__ cen) {
    __shared__ float st[16 * 673];
    int xc = blockIdx.x, h = blockIdx.y, b = blockIdx.z;
    int s = c_shift[h];
    int bh = b * Hh + h;
    int t = threadIdx.x;
    int c2 = t & 15;
    int c1b = ((t >> 4) & 3) * 4;
    int qq = t >> 6;
    const float* cb = cen + (size_t)b * Cc * NPIX;

    float acc[52];
    #pragma unroll
    for (int i = 0; i < 52; i++) acc[i] = 0.0f;

    for (int qx = xc * 8; qx < xc * 8 + 8; qx++) {
        __syncthreads();
        for (int idx = t; idx < 16 * 673; idx += 256) {
            int c = idx / 673;
            int rm = idx - c * 673;
            float v = 0.0f;
            if (rm < 672) {
                int k = rm / 224, j = rm - k * 224;
                int r = qx + k * s;
                int y = j - 16;
                if (r < WD && y >= 0 && y < HT)
                    v = cb[((size_t)c * WD + r) * HT + y];
            }
            st[idx] = v;
        }
        __syncthreads();

        const float* a0 = st + (c1b + 0) * 673 + 16;
        const float* a1 = st + (c1b + 1) * 673 + 16;
        const float* a2 = st + (c1b + 2) * 673 + 16;
        const float* a3 = st + (c1b + 3) * 673 + 16;
        const float* b0 = st + c2 * 673 + 16;
        const float* b1 = b0 + 224;
        const float* b2 = b1 + 224;
        #pragma unroll 2
        for (int qy = qq * 48; qy < qq * 48 + 48; qy++) {
            float av0 = a0[qy], av1 = a1[qy], av2 = a2[qy], av3 = a3[qy];
            float bv;
            #define CORR_LAG(L, EXPR) \
                bv = (EXPR); \
                acc[0 * 13 + (L)] = fmaf(av0, bv, acc[0 * 13 + (L)]); \
                acc[1 * 13 + (L)] = fmaf(av1, bv, acc[1 * 13 + (L)]); \
                acc[2 * 13 + (L)] = fmaf(av2, bv, acc[2 * 13 + (L)]); \
                acc[3 * 13 + (L)] = fmaf(av3, bv, acc[3 * 13 + (L)]);
            CORR_LAG(0,  b0[qy])
            CORR_LAG(1,  b0[qy + s])
            CORR_LAG(2,  b0[qy + 2 * s])
            CORR_LAG(3,  b1[qy - 2 * s])
            CORR_LAG(4,  b1[qy - s])
            CORR_LAG(5,  b1[qy])
            CORR_LAG(6,  b1[qy + s])
            CORR_LAG(7,  b1[qy + 2 * s])
            CORR_LAG(8,  b2[qy - 2 * s])
            CORR_LAG(9,  b2[qy - s])
            CORR_LAG(10, b2[qy])
            CORR_LAG(11, b2[qy + s])
            CORR_LAG(12, b2[qy + 2 * s])
            #undef CORR_LAG
        }
    }
    #pragma unroll
    for (int i = 0; i < 4; i++) {
        float* dst = &g_F[bh][(c1b + i) * 16 + c2][12];
        #pragma unroll
        for (int l = 0; l < 13; l++) atomicAdd(dst + l, acc[i * 13 + l]);
    }
}

// ---------------- kernel 3b: x-border strips, all 25 lags ----------------
// grid (64 = side(2) x ychunk(4) x qslot(8), Hh, Bb); ONE fill per block.
__global__ void __launch_bounds__(256) k_stripx(const float* __restrict__ cen) {
    __shared__ float yw[16 * 401];    // 5 x-rows x 80 y per channel, stride 401
    int bx = blockIdx.x;
    int side = bx & 1, chunk = (bx >> 1) & 3, qslot = bx >> 3;
    int h = blockIdx.y, b = blockIdx.z;
    int s = c_shift[h];
    if (qslot >= s) return;
    int bh = b * Hh + h;
    int t = threadIdx.x;
    int c1 = t & 15, c2 = t >> 4;
    const float* cb = cen + (size_t)b * Cc * NPIX;
    int x0 = side ? (WD - s) : 0;
    int qx = x0 + qslot;
    int ybase = chunk * 48 - 16;

    for (int idx = t; idx < 16 * 401; idx += 256) {
        int c = idx / 401;
        int rm = idx - c * 401;
        float v = 0.0f;
        if (rm < 400) {
            int k = rm / 80, j = rm - k * 80;
            int r = qx + (k - 2) * s;
            int y = ybase + j;
            if (r >= 0 && r < WD && y >= 0 && y < HT)
                v = cb[((size_t)c * WD + r) * HT + y];
        }
        yw[idx] = v;
    }
    __syncthreads();

    float acc[25];
    #pragma unroll
    for (int i = 0; i < 25; i++) acc[i] = 0.0f;

    const float* ar = yw + c1 * 401 + 2 * 80 + 16;
    const float* bb = yw + c2 * 401 + 16;
    for (int jj = 0; jj < 48; jj++) {
        float a = ar[jj];
        #pragma unroll
        for (int ix = 0; ix < 5; ix++) {
            const float* br = bb + ix * 80 + jj;
            #pragma unroll
            for (int iy = 0; iy < 5; iy++)
                acc[ix * 5 + iy] = fmaf(a, br[(iy - 2) * s], acc[ix * 5 + iy]);
        }
    }
    float* dst = &g_SxS[side][bh][c1 * 16 + c2][0];
    #pragma unroll
    for (int i = 0; i < 25; i++) atomicAdd(dst + i, acc[i]);
}

// ---------------- kernel 3c: y-border strips, all 25 lags ----------------
// grid (32 = side(2) x xchunk(16 of 12), Hh, Bb); ONE fill per block covering
// rows [qx0-2s, qx0+12+2s) x y-window [y0-2s, y0+3s). Dynamic smem, worst 112.7KB.
__global__ void __launch_bounds__(256) k_stripy(const float* __restrict__ cen) {
    extern __shared__ float yw[];
    int bx = blockIdx.x;
    int side = bx & 1, chunk = bx >> 1;
    int h = blockIdx.y, b = blockIdx.z;
    int s = c_shift[h];
    int bh = b * Hh + h;
    int t = threadIdx.x;
    int c1 = t & 15, c2 = t >> 4;
    const float* cb = cen + (size_t)b * Cc * NPIX;
    int y0 = side ? (HT - s) : 0;
    int jy0 = y0 - 2 * s;
    int qx0 = chunk * 12;
    int rows = 12 + 4 * s;
    int ww = 5 * s;
    int stride = rows * ww + 1;

    for (int idx = t; idx < 16 * stride; idx += 256) {
        int c = idx / stride;
        int rm = idx - c * stride;
        float v = 0.0f;
        if (rm < rows * ww) {
            int rr = rm / ww, j = rm - rr * ww;
            int r = qx0 - 2 * s + rr;
            int y = jy0 + j;
            if (r >= 0 && r < WD && y >= 0 && y < HT)
                v = cb[((size_t)c * WD + r) * HT + y];
        }
        yw[idx] = v;
    }
    __syncthreads();

    float acc[25];
    #pragma unroll
    for (int i = 0; i < 25; i++) acc[i] = 0.0f;

    const float* base1 = yw + c1 * stride;
    const float* base2 = yw + c2 * stride;
    for (int dx = 0; dx < 12; dx++) {
        const float* ar = base1 + (dx + 2 * s) * ww + 2 * s;
        for (int jj = 0; jj < s; jj++) {
            float a = ar[jj];
            #pragma unroll
            for (int ix = 0; ix < 5; ix++) {
                const float* br = base2 + (dx + ix * s) * ww + jj;
                #pragma unroll
                for (int iy = 0; iy < 5; iy++)
                    acc[ix * 5 + iy] = fmaf(a, br[iy * s], acc[ix * 5 + iy]);
            }
        }
    }
    float* dst = &g_SyS[side][bh][c1 * 16 + c2][0];
    #pragma unroll
    for (int i = 0; i < 25; i++) atomicAdd(dst + i, acc[i]);
}

// ---------------- kernel 3d: s x s corner patches, all 25 lags ----------------
// grid (32 = corner(4) x islot(8), Hh, Bb); early exit islot>=s; atomicAdd.
__global__ void __launch_bounds__(256) k_corner(const float* __restrict__ cen) {
    int bx = blockIdx.x;
    int corner = bx & 3, islot = bx >> 2;
    int cx = corner >> 1, cy = corner & 1;
    int h = blockIdx.y, b = blockIdx.z;
    int s = c_shift[h];
    if (islot >= s) return;
    int bh = b * Hh + h;
    int t = threadIdx.x;
    int c1 = t & 15, c2 = t >> 4;
    const float* cb = cen + (size_t)b * Cc * NPIX;
    int x0 = cx ? (WD - s) : 0;
    int y0 = cy ? (HT - s) : 0;

    float acc[25];
    #pragma unroll
    for (int i = 0; i < 25; i++) acc[i] = 0.0f;

    int qx = x0 + islot;
    for (int j = 0; j < s; j++) {
        int qy = y0 + j;
        float a = cb[((size_t)c1 * WD + qx) * HT + qy];
        #pragma unroll
        for (int ix = 0; ix < 5; ix++) {
            int bxx = qx + (ix - 2) * s;
            #pragma unroll
            for (int iy = 0; iy < 5; iy++) {
                int by = qy + (iy - 2) * s;
                float bv = (bxx >= 0 && bxx < WD && by >= 0 && by < HT)
                           ? cb[((size_t)c2 * WD + bxx) * HT + by] : 0.0f;
                acc[ix * 5 + iy] = fmaf(a, bv, acc[ix * 5 + iy]);
            }
        }
    }
    float* dst = &g_Cn[corner][bh][c1 * 16 + c2][0];
    #pragma unroll
    for (int i = 0; i < 25; i++) atomicAdd(dst + i, acc[i]);
}

// ---------------- kernel 3e: mirror fill F for dd<12 ----------------
__global__ void k_mirrorF() {
    int bh = blockIdx.x;
    int p = threadIdx.x;
    int cA = p >> 4, cB = p & 15;
    int ps = cB * 16 + cA;
    #pragma unroll
    for (int d = 0; d < 12; d++)
        g_F[bh][p][d] = g_F[bh][ps][24 - d];
}

// ---------------- kernel 4: per (b,h) attention head (assembles S from corr tables) ----------------
__global__ void __launch_bounds__(512) k_attn(const float* __restrict__ w_out) {
    extern __shared__ float pool[];
    float* S_sm  = pool;
    float* Wk_sm = pool + 20880;
    float* Wq_sm = pool + 39440;
    float* T_sm  = pool + 41744;
    float* G     = pool + 44048;
    float* M     = Wk_sm;
    __shared__ float nq[16], nk[128], red[512];

    int bh = blockIdx.x;
    int b = bh >> 2, h = bh & 3;
    int t = threadIdx.x;

    for (int idx = t; idx < SDIM * SDIM; idx += 512) {
        int r = idx / SDIM, c = idx - r * SDIM;
        int c1 = r / 9, d1 = r - c1 * 9;
        int c2 = c / 9, d2 = c - c2 * 9;
        int o1x = d1 / 3 - 1, o1y = d1 % 3 - 1;
        int o2x = d2 / 3 - 1, o2y = d2 % 3 - 1;
        int dd = (o2x - o1x + 2) * 5 + (o2y - o1y + 2);
        int p = c1 * 16 + c2;
        float v = g_F[bh][p][dd];
        if (o1x > 0)      v -= g_SxS[0][bh][p][dd];
        else if (o1x < 0) v -= g_SxS[1][bh][p][dd];
        if (o1y > 0)      v -= g_SyS[0][bh][p][dd];
        else if (o1y < 0) v -= g_SyS[1][bh][p][dd];
        if (o1x != 0 && o1y != 0) {
            int ci = ((o1x > 0) ? 0 : 2) + ((o1y > 0) ? 0 : 1);
            v += g_Cn[ci][bh][p][dd];
        }
        S_sm[r * 145 + c] = v;
    }
    for (int idx = t; idx < 128 * SDIM; idx += 512) {
        int r = idx / SDIM, c = idx - r * SDIM;
        Wk_sm[r * 145 + c] = (&g_Wk[h][0][0])[idx];
    }
    for (int idx = t; idx < 16 * SDIM; idx += 512)
        Wq_sm[idx] = (&g_Wq[h][0][0])[idx];
    __syncthreads();

    for (int g = t; g < 576; g += 512) {
        int q = g / 36, i0 = (g - q * 36) * 4;
        float a0 = 0.0f, a1 = 0.0f, a2 = 0.0f, a3 = 0.0f;
        const float* wqr = Wq_sm + q * SDIM;
        #pragma unroll 4
        for (int j = 0; j < SDIM; j++) {
            float wv = wqr[j];
            const float* sr = S_sm + j * 145 + i0;
            a0 = fmaf(wv, sr[0], a0);
            a1 = fmaf(wv, sr[1], a1);
            a2 = fmaf(wv, sr[2], a2);
            a3 = fmaf(wv, sr[3], a3);
        }
        float* tr = T_sm + q * SDIM + i0;
        tr[0] = a0; tr[1] = a1; tr[2] = a2; tr[3] = a3;
    }
    __syncthreads();

    if (t < 16) {
        float a = 0.0f;
        for (int i = 0; i < SDIM; i++)
            a = fmaf(T_sm[t * SDIM + i], Wq_sm[t * SDIM + i], a);
        nq[t] = fmaxf(sqrtf(fmaxf(a, 0.0f)), 1e-12f);
    }

    {
        int q = t >> 5, k0 = (t & 31) * 4;
        float a0 = 0.0f, a1 = 0.0f, a2 = 0.0f, a3 = 0.0f;
        const float* tq = T_sm + q * SDIM;
        const float* w0 = Wk_sm + (k0 + 0) * 145;
        const float* w1 = Wk_sm + (k0 + 1) * 145;
        const float* w2 = Wk_sm + (k0 + 2) * 145;
        const float* w3 = Wk_sm + (k0 + 3) * 145;
        #pragma unroll 4
        for (int i = 0; i < SDIM; i++) {
            float tv = tq[i];
            a0 = fmaf(tv, w0[i], a0);
            a1 = fmaf(tv, w1[i], a1);
            a2 = fmaf(tv, w2[i], a2);
            a3 = fmaf(tv, w3[i], a3);
        }
        G[q * 128 + k0 + 0] = a0;
        G[q * 128 + k0 + 1] = a1;
        G[q * 128 + k0 + 2] = a2;
        G[q * 128 + k0 + 3] = a3;
    }

    {
        int k = t & 127, g = t >> 7;
        const float* wk_r = Wk_sm + k * 145;
        float a = 0.0f;
        #pragma unroll 1
        for (int qd = 0; qd < 9; qd++) {
            int i0 = g * 36 + qd * 4;
            float r0 = 0.0f, r1 = 0.0f, r2 = 0.0f, r3 = 0.0f;
            const float* s0 = S_sm + (i0 + 0) * 145;
            const float* s1 = S_sm + (i0 + 1) * 145;
            const float* s2 = S_sm + (i0 + 2) * 145;
            const float* s3 = S_sm + (i0 + 3) * 145;
            #pragma unroll 4
            for (int j = 0; j < SDIM; j++) {
                float wv = wk_r[j];
                r0 = fmaf(s0[j], wv, r0);
                r1 = fmaf(s1[j], wv, r1);
                r2 = fmaf(s2[j], wv, r2);
                r3 = fmaf(s3[j], wv, r3);
            }
            a = fmaf(wk_r[i0 + 0], r0, a);
            a = fmaf(wk_r[i0 + 1], r1, a);
            a = fmaf(wk_r[i0 + 2], r2, a);
            a = fmaf(wk_r[i0 + 3], r3, a);
        }
        red[t] = a;
    }
    __syncthreads();
    if (t < 128) {
        float sum = red[t] + red[t + 128] + red[t + 256] + red[t + 384];
        nk[t] = fmaxf(sqrtf(fmaxf(sum, 0.0f)), 1e-12f);
    }
    __syncthreads();

    for (int idx = t; idx < 2048; idx += 512) {
        int q = idx >> 7, k = idx & 127;
        G[idx] = G[idx] / (nq[q] * nk[k] * 192.0f);
    }
    __syncthreads();

    float lsum = 0.0f;
    for (int idx = t; idx < 2048; idx += 512) lsum += G[idx];
    red[t] = lsum; __syncthreads();
    for (int st = 256; st > 0; st >>= 1) { if (t < st) red[t] += red[t + st]; __syncthreads(); }
    float mean = red[0] * (1.0f / 2048.0f);
    __syncthreads();
    float lss = 0.0f;
    for (int idx = t; idx < 2048; idx += 512) { float d = G[idx] - mean; lss = fmaf(d, d, lss); }
    red[t] = lss; __syncthreads();
    for (int st = 256; st > 0; st >>= 1) { if (t < st) red[t] += red[t + st]; __syncthreads(); }
    float var = red[0] * (1.0f / 2048.0f);
    float iscale = rsqrtf(var + 1e-5f);
    __syncthreads();
    for (int idx = t; idx < 2048; idx += 512)
        G[idx] = (G[idx] - mean) * iscale;
    __syncthreads();

    int wid = t >> 5, lane = t & 31;
    {
        int q = wid;
        float m = -1e30f;
        for (int k = lane; k < 128; k += 32) m = fmaxf(m, G[q * 128 + k]);
        #pragma unroll
        for (int o = 16; o > 0; o >>= 1) m = fmaxf(m, __shfl_xor_sync(0xffffffffu, m, o));
        float ssum = 0.0f;
        for (int k = lane; k < 128; k += 32) {
            float e = expf(G[q * 128 + k] - m);
            G[q * 128 + k] = e;
            ssum += e;
        }
        #pragma unroll
        for (int o = 16; o > 0; o >>= 1) ssum += __shfl_xor_sync(0xffffffffu, ssum, o);
        float inv = 1.0f / ssum;
        for (int k = lane; k < 128; k += 32) G[q * 128 + k] *= inv;
    }
    __syncthreads();

    float mv[8];
    {
        #pragma unroll
        for (int r = 0; r < 8; r++) {
            int idx = t + r * 512;
            int o = idx >> 7, k = idx & 127;
            float a = 0.0f;
            #pragma unroll
            for (int q = 0; q < 16; q++)
                a = fmaf(w_out[o * 64 + h * 16 + q], G[q * 128 + k], a);
            mv[r] = a;
        }
    }
    __syncthreads();
    #pragma unroll
    for (int r = 0; r < 8; r++) M[t + r * 512] = mv[r];
    __syncthreads();

    for (int g = t; g < OCH * 36; g += 512) {
        int o = g / 36, i0 = (g - o * 36) * 4;
        float a0 = 0.0f, a1 = 0.0f, a2 = 0.0f, a3 = 0.0f;
        const float* mo = M + o * 128;
        #pragma unroll 4
        for (int k = 0; k < 128; k++) {
            float mvv = mo[k];
            const float* wvr = &g_Wv[h][k][i0];
            a0 = fmaf(mvv, wvr[0], a0);
            a1 = fmaf(mvv, wvr[1], a1);
            a2 = fmaf(mvv, wvr[2], a2);
            a3 = fmaf(mvv, wvr[3], a3);
        }
        float* w2r = &g_W2[b][h][o][i0];
        w2r[0] = a0; w2r[1] = a1; w2r[2] = a2; w2r[3] = a3;
    }
}

// ---------------- kernel 5: fused output conv (f32x2) + BN stats ----------------
__global__ void __launch_bounds__(256) k_out(const float* __restrict__ cen, float* __restrict__ out) {
    extern __shared__ float dsm[];
    float* insm = dsm;
    float* W2sm = dsm + Cc * 3 * W2;

    int xg = blockIdx.x, b = blockIdx.y;
    int t = threadIdx.x;
    int ty = t & 31, to = t >> 5;
    const float* cb = cen + (size_t)b * Cc * NPIX;

    for (int xr = 0; xr < 4; xr++) {
        int x = xg * 4 + xr;
        ull acc2[4][3];
        #pragma unroll
        for (int oo = 0; oo < 4; oo++)
            #pragma unroll
            for (int j = 0; j < 3; j++) acc2[oo][j] = 0ull;

        for (int h = 0; h < Hh; h++) {
            int s = c_shift[h];
            int plen = HT + 2 * s;
            __syncthreads();
            for (int idx = t; idx < Cc * 3 * plen; idx += 256) {
                int c = idx / (3 * plen);
                int rem = idx - c * 3 * plen;
                int r = rem / plen;
                int p = rem - r * plen;
                int xx = x + (r - 1) * s;
                int y = p - s;
                float v = 0.0f;
                if (xx >= 0 && xx < WD && y >= 0 && y < HT)
                    v = cb[((size_t)c * WD + xx) * HT + y];
                insm[c * (3 * W2) + r * W2 + p] = v;
            }
            for (int idx = t; idx < OCH * SDIM; idx += 256)
                W2sm[idx] = (&g_W2[b][h][0][0])[idx];
            __syncthreads();

            int ybase = ty * 6;
            #pragma unroll 1
            for (int c = 0; c < Cc; c++) {
                const float* pc = insm + c * (3 * W2);
                #pragma unroll
                for (int d = 0; d < 9; d++) {
                    const float* px = pc + (d / 3) * W2 + (d % 3) * s + ybase;
                    float w0 = W2sm[(to * 4 + 0) * SDIM + c * 9 + d];
                    float w1 = W2sm[(to * 4 + 1) * SDIM + c * 9 + d];
                    float w2 = W2sm[(to * 4 + 2) * SDIM + c * 9 + d];
                    float w3 = W2sm[(to * 4 + 3) * SDIM + c * 9 + d];
                    ull w0p = pk2(w0, w0), w1p = pk2(w1, w1);
                    ull w2p = pk2(w2, w2), w3p = pk2(w3, w3);
                    #pragma unroll
                    for (int j = 0; j < 3; j++) {
                        ull xv = pk2(px[2 * j], px[2 * j + 1]);
                        acc2[0][j] = ffma2(w0p, xv, acc2[0][j]);
                        acc2[1][j] = ffma2(w1p, xv, acc2[1][j]);
                        acc2[2][j] = ffma2(w2p, xv, acc2[2][j]);
                        acc2[3][j] = ffma2(w3p, xv, acc2[3][j]);
                    }
                }
            }
        }

        #pragma unroll
        for (int oo = 0; oo < 4; oo++) {
            int o = to * 4 + oo;
            float s1 = 0.0f, s2 = 0.0f;
            float* op = out + (((size_t)b * OCH + o) * WD + x) * HT + ty * 6;
            #pragma unroll
            for (int j = 0; j < 3; j++) {
                float lo, hi;
                upk2(acc2[oo][j], lo, hi);
                op[2 * j]     = lo;
                op[2 * j + 1] = hi;
                s1 += lo + hi;
                s2 = fmaf(lo, lo, s2);
                s2 = fmaf(hi, hi, s2);
            }
            #pragma unroll
            for (int off2 = 16; off2 > 0; off2 >>= 1) {
                s1 += __shfl_xor_sync(0xffffffffu, s1, off2);
                s2 += __shfl_xor_sync(0xffffffffu, s2, off2);
            }
            if (ty == 0) {
                atomicAdd(&g_bnsum[o], s1);
                atomicAdd(&g_bnsq[o], s2);
            }
        }
    }
}

// ---------------- kernel 6: batchnorm + ReLU ----------------
__global__ void k_bn(float* __restrict__ out, const float* __restrict__ gamma,
                     const float* __restrict__ beta) {
    __shared__ float ssc[OCH], sbi[OCH];
    if (threadIdx.x < OCH) {
        int o = threadIdx.x;
        float invN = 1.0f / ((float)Bb * NPIX);
        float m = g_bnsum[o] * invN;
        float v = g_bnsq[o] * invN - m * m;
        float sc = gamma[o] * rsqrtf(v + 1e-5f);
        ssc[o] = sc;
        sbi[o] = beta[o] - m * sc;
    }
    __syncthreads();
    size_t total = (size_t)Bb * OCH * NPIX;
    for (size_t i = (size_t)blockIdx.x * blockDim.x + threadIdx.x; i < total;
         i += (size_t)gridDim.x * blockDim.x) {
        int o = (int)((i / NPIX) & 31);
        float v = fmaf(out[i], ssc[o], sbi[o]);
        out[i] = fmaxf(v, 0.0f);
    }
}

// ---------------- launch ----------------
extern "C" void kernel_launch(void* const* d_in, const int* in_sizes, int n_in,
                              void* d_out, int out_size) {
    (void)in_sizes; (void)n_in; (void)out_size;
    const float* cen   = (const float*)d_in[0];
    const float* wq    = (const float*)d_in[1];
    const float* wk    = (const float*)d_in[2];
    const float* wv    = (const float*)d_in[3];
    const float* sum_w = (const float*)d_in[4];
    const float* w_out = (const float*)d_in[5];
    const float* gamma = (const float*)d_in[6];
    const float* beta  = (const float*)d_in[7];
    float* out = (float*)d_out;

    int dynsmem_out    = (Cc * 3 * W2 + OCH * SDIM) * (int)sizeof(float);
    int dynsmem_attn   = 46096 * (int)sizeof(float);
    int dynsmem_stripy = 16 * (44 * 40 + 1) * (int)sizeof(float);   // worst case s=8
    cudaFuncSetAttribute(k_out,    cudaFuncAttributeMaxDynamicSharedMemorySize, dynsmem_out);
    cudaFuncSetAttribute(k_attn,   cudaFuncAttributeMaxDynamicSharedMemorySize, dynsmem_attn);
    cudaFuncSetAttribute(k_stripy, cudaFuncAttributeMaxDynamicSharedMemorySize, dynsmem_stripy);

    k_prep<<<4, 256>>>(wq, wk, wv, sum_w);
    k_zero<<<512, 256>>>();
    k_corrF<<<dim3(24, 4, 8), 256>>>(cen);
    k_stripx<<<dim3(64, 4, 8), 256>>>(cen);
    k_stripy<<<dim3(32, 4, 8), 256, dynsmem_stripy>>>(cen);
    k_corner<<<dim3(32, 4, 8), 256>>>(cen);
    k_mirrorF<<<32, 256>>>();
    k_attn<<<32, 512, dynsmem_attn>>>(w_out);
    k_out<<<dim3(48, 8), 256, dynsmem_out>>>(cen, out);
    k_bn<<<2048, 256>>>(out, gamma, beta);
}